// round 9
// baseline (speedup 1.0000x reference)
#include <cuda_runtime.h>
#include <cuda_bf16.h>
#include <math_constants.h>
#include <cstdint>

// Problem constants
#define BATCH 2
#define SEQ   2048
#define MODEL 1024
#define HEADS 16
#define HDIM  64
#define ROWS  (BATCH*SEQ)          // 4096
#define QKVN  (3*MODEL)            // 3072
#define KDIM  1024

// ---------------------------------------------------------------------------
// Scratch (device globals: allocation-free)
// ---------------------------------------------------------------------------
__device__ __nv_bfloat16 g_qh[(size_t)ROWS * QKVN];   // qkv hi (q pre-scaled 1/8)
__device__ __nv_bfloat16 g_ql[(size_t)ROWS * QKVN];   // qkv lo
__device__ __nv_bfloat16 g_xh[(size_t)ROWS * KDIM];
__device__ __nv_bfloat16 g_xl[(size_t)ROWS * KDIM];
__device__ __nv_bfloat16 g_wah[(size_t)QKVN * KDIM];
__device__ __nv_bfloat16 g_wal[(size_t)QKVN * KDIM];
__device__ __nv_bfloat16 g_wph[(size_t)MODEL * KDIM];
__device__ __nv_bfloat16 g_wpl[(size_t)MODEL * KDIM];
__device__ __nv_bfloat16 g_zh[(size_t)ROWS * MODEL];
__device__ __nv_bfloat16 g_zl[(size_t)ROWS * MODEL];

// ---------------------------------------------------------------------------
// Helpers
// ---------------------------------------------------------------------------
__device__ __forceinline__ uint32_t smem_u32(const void* p) {
    uint32_t a;
    asm("{ .reg .u64 t; cvta.to.shared.u64 t, %1; cvt.u32.u64 %0, t; }"
        : "=r"(a) : "l"(p));
    return a;
}
__device__ __forceinline__ void ldm_x4(uint32_t* r, uint32_t a) {
    asm volatile("ldmatrix.sync.aligned.m8n8.x4.shared.b16 {%0,%1,%2,%3}, [%4];"
        : "=r"(r[0]), "=r"(r[1]), "=r"(r[2]), "=r"(r[3]) : "r"(a));
}
__device__ __forceinline__ void ldm_x4_t(uint32_t* r, uint32_t a) {
    asm volatile("ldmatrix.sync.aligned.m8n8.x4.trans.shared.b16 {%0,%1,%2,%3}, [%4];"
        : "=r"(r[0]), "=r"(r[1]), "=r"(r[2]), "=r"(r[3]) : "r"(a));
}
__device__ __forceinline__ void mma16816(float* c, const uint32_t* a, const uint32_t* b) {
    asm volatile("mma.sync.aligned.m16n8k16.row.col.f32.bf16.bf16.f32 "
        "{%0,%1,%2,%3}, {%4,%5,%6,%7}, {%8,%9}, {%0,%1,%2,%3};"
        : "+f"(c[0]), "+f"(c[1]), "+f"(c[2]), "+f"(c[3])
        : "r"(a[0]), "r"(a[1]), "r"(a[2]), "r"(a[3]), "r"(b[0]), "r"(b[1]));
}
__device__ __forceinline__ void cp16(uint32_t saddr, const void* gaddr) {
    asm volatile("cp.async.cg.shared.global [%0], [%1], 16;" :: "r"(saddr), "l"(gaddr));
}
__device__ __forceinline__ uint32_t packbf(float a, float b) {
    uint32_t r;
    asm("cvt.rn.satfinite.bf16x2.f32 %0, %1, %2;" : "=r"(r) : "f"(b), "f"(a));
    return r;
}
__device__ __forceinline__ void split4(float4 v, uint2& h, uint2& l) {
    __nv_bfloat16 h0 = __float2bfloat16(v.x), h1 = __float2bfloat16(v.y);
    __nv_bfloat16 h2 = __float2bfloat16(v.z), h3 = __float2bfloat16(v.w);
    __nv_bfloat16 l0 = __float2bfloat16(v.x - __bfloat162float(h0));
    __nv_bfloat16 l1 = __float2bfloat16(v.y - __bfloat162float(h1));
    __nv_bfloat16 l2 = __float2bfloat16(v.z - __bfloat162float(h2));
    __nv_bfloat16 l3 = __float2bfloat16(v.w - __bfloat162float(h3));
    __nv_bfloat162 ph0 = __halves2bfloat162(h0, h1), ph1 = __halves2bfloat162(h2, h3);
    __nv_bfloat162 pl0 = __halves2bfloat162(l0, l1), pl1 = __halves2bfloat162(l2, l3);
    h.x = *reinterpret_cast<uint32_t*>(&ph0); h.y = *reinterpret_cast<uint32_t*>(&ph1);
    l.x = *reinterpret_cast<uint32_t*>(&pl0); l.y = *reinterpret_cast<uint32_t*>(&pl1);
}

// ---------------------------------------------------------------------------
// Prep kernels
// ---------------------------------------------------------------------------
__global__ void split_convert(const float* __restrict__ x,
                              __nv_bfloat16* __restrict__ h,
                              __nv_bfloat16* __restrict__ l, int n4)
{
    int i = blockIdx.x * blockDim.x + threadIdx.x;
    if (i >= n4) return;
    float4 v = ((const float4*)x)[i];
    uint2 uh, ul;
    split4(v, uh, ul);
    ((uint2*)h)[i] = uh;
    ((uint2*)l)[i] = ul;
}

__global__ void transpose_split(const float* __restrict__ W,
                                __nv_bfloat16* __restrict__ Th,
                                __nv_bfloat16* __restrict__ Tl,
                                int Kd, int Nd)
{
    __shared__ float t[32][33];
    int n0 = blockIdx.x * 32, k0 = blockIdx.y * 32;
    int tx = threadIdx.x, ty = threadIdx.y;
#pragma unroll
    for (int j = 0; j < 32; j += 8)
        t[ty + j][tx] = W[(size_t)(k0 + ty + j) * Nd + n0 + tx];
    __syncthreads();
#pragma unroll
    for (int j = 0; j < 32; j += 8) {
        float v = t[tx][ty + j];
        int n = n0 + ty + j, k = k0 + tx;
        __nv_bfloat16 hb = __float2bfloat16(v);
        __nv_bfloat16 lb = __float2bfloat16(v - __bfloat162float(hb));
        Th[(size_t)n * Kd + k] = hb;
        Tl[(size_t)n * Kd + k] = lb;
    }
}

// ---------------------------------------------------------------------------
// mma.sync split-bf16 GEMM: BK=32, double-buffered smem, 2 CTAs/SM.
// MODE 0: C = fp32 (acc + bias)
// MODE 1: Ch/Cl = bf16 hi/lo of (acc + bias) * (col<MODEL ? 0.125 : 1)
// ---------------------------------------------------------------------------
#define GPITCH 80                 // 64 B data + 16 B pad
#define GTILEB (128 * GPITCH)     // 10240 B
#define GSTAGEB (4 * GTILEB)      // 40960 B
#define GSMEM  (2 * GSTAGEB)      // 81920 B
#define NCHUNK 32                 // 1024 / 32

template<int MODE>
__global__ __launch_bounds__(256, 2) void gemm_mma(
    const __nv_bfloat16* __restrict__ Ah, const __nv_bfloat16* __restrict__ Al,
    const __nv_bfloat16* __restrict__ Bh, const __nv_bfloat16* __restrict__ Bl,
    const float* __restrict__ bias, float* __restrict__ C,
    __nv_bfloat16* __restrict__ Ch, __nv_bfloat16* __restrict__ Cl, int Nd)
{
    extern __shared__ char smem[];
    const uint32_t sbase = smem_u32(smem);
    const int tid  = threadIdx.x;
    const int wid  = tid >> 5, lane = tid & 31;
    const int bn   = blockIdx.x * 128;
    const int bm   = blockIdx.y * 128;
    const int wm0  = (wid & 3) * 32;
    const int wn0  = (wid >> 2) * 64;

    // loader mapping: 2 threads per row; 2 x 16B chunks per thread per tile
    const int lrow = tid >> 1;            // 0..127
    const int lc2  = (tid & 1) * 2;       // chunk 0..1 or 2..3

    const __nv_bfloat16* srcA_h = Ah + (size_t)(bm + lrow) * KDIM + lc2 * 8;
    const __nv_bfloat16* srcA_l = Al + (size_t)(bm + lrow) * KDIM + lc2 * 8;
    const __nv_bfloat16* srcB_h = Bh + (size_t)(bn + lrow) * KDIM + lc2 * 8;
    const __nv_bfloat16* srcB_l = Bl + (size_t)(bn + lrow) * KDIM + lc2 * 8;

    const int arow  = (lane & 7) + ((lane >> 3) & 1) * 8;
    const int acolB = ((lane >> 4) & 1) * 16;
    const int brow  = (lane & 7) + ((lane >> 4) & 1) * 8;
    const int bcolB = ((lane >> 3) & 1) * 16;

    float acc[16][4];
#pragma unroll
    for (int i = 0; i < 16; i++)
#pragma unroll
        for (int j = 0; j < 4; j++) acc[i][j] = 0.f;

    auto issue = [&](int stage, int k0) {
        uint32_t so = sbase + stage * GSTAGEB + lrow * GPITCH + lc2 * 16;
#pragma unroll
        for (int j = 0; j < 2; j++) {
            uint32_t sa = so + j * 16;
            size_t   go = (size_t)k0 + j * 8;
            cp16(sa,               srcA_h + go);
            cp16(sa + GTILEB,      srcA_l + go);
            cp16(sa + 2 * GTILEB,  srcB_h + go);
            cp16(sa + 3 * GTILEB,  srcB_l + go);
        }
        asm volatile("cp.async.commit_group;" ::: "memory");
    };

    issue(0, 0);

    for (int c = 0; c < NCHUNK; c++) {
        if (c + 1 < NCHUNK) {
            issue((c + 1) & 1, (c + 1) * 32);
            asm volatile("cp.async.wait_group 1;" ::: "memory");
        } else {
            asm volatile("cp.async.wait_group 0;" ::: "memory");
        }
        __syncthreads();

        const uint32_t ab  = sbase + (c & 1) * GSTAGEB;
        const uint32_t alb = ab + GTILEB;
        const uint32_t bb  = ab + 2 * GTILEB;
        const uint32_t blb = ab + 3 * GTILEB;

#pragma unroll
        for (int ks = 0; ks < 2; ks++) {
            uint32_t fah[2][4], fal[2][4], fbh[4][4], fbl[4][4];
#pragma unroll
            for (int ma = 0; ma < 2; ma++) {
                uint32_t off = (uint32_t)(wm0 + ma * 16 + arow) * GPITCH + ks * 32 + acolB;
                ldm_x4(fah[ma], ab + off);
                ldm_x4(fal[ma], alb + off);
            }
#pragma unroll
            for (int na = 0; na < 4; na++) {
                uint32_t off = (uint32_t)(wn0 + na * 16 + brow) * GPITCH + ks * 32 + bcolB;
                ldm_x4(fbh[na], bb + off);
                ldm_x4(fbl[na], blb + off);
            }
#pragma unroll
            for (int ma = 0; ma < 2; ma++) {
#pragma unroll
                for (int na = 0; na < 4; na++) {
                    float* c0 = acc[ma * 8 + na * 2];
                    float* c1 = acc[ma * 8 + na * 2 + 1];
                    mma16816(c0, fah[ma], fbh[na]);
                    mma16816(c1, fah[ma], fbh[na] + 2);
                    mma16816(c0, fah[ma], fbl[na]);
                    mma16816(c1, fah[ma], fbl[na] + 2);
                    mma16816(c0, fal[ma], fbh[na]);
                    mma16816(c1, fal[ma], fbh[na] + 2);
                }
            }
        }
        __syncthreads();
    }

    const int er = bm + wm0 + (lane >> 2);
    const int ec = bn + wn0 + (lane & 3) * 2;
#pragma unroll
    for (int ma = 0; ma < 2; ma++) {
#pragma unroll
        for (int na = 0; na < 8; na++) {
            const float* a4 = acc[ma * 8 + na];
            int row = er + ma * 16;
            int col = ec + na * 8;
            float b0 = __ldg(bias + col), b1 = __ldg(bias + col + 1);
            if (MODE == 0) {
                float2 v0 = make_float2(a4[0] + b0, a4[1] + b1);
                float2 v1 = make_float2(a4[2] + b0, a4[3] + b1);
                *(float2*)(C + (size_t)row * Nd + col)       = v0;
                *(float2*)(C + (size_t)(row + 8) * Nd + col) = v1;
            } else {
                float sc = (col < MODEL) ? 0.125f : 1.f;
                float v0 = (a4[0] + b0) * sc, v1 = (a4[1] + b1) * sc;
                float v2 = (a4[2] + b0) * sc, v3 = (a4[3] + b1) * sc;
                __nv_bfloat16 h0 = __float2bfloat16(v0), h1 = __float2bfloat16(v1);
                __nv_bfloat16 h2 = __float2bfloat16(v2), h3 = __float2bfloat16(v3);
                __nv_bfloat162 p0 = __halves2bfloat162(h0, h1);
                __nv_bfloat162 p1 = __halves2bfloat162(h2, h3);
                uint32_t wl0 = packbf(v0 - __bfloat162float(h0), v1 - __bfloat162float(h1));
                uint32_t wl1 = packbf(v2 - __bfloat162float(h2), v3 - __bfloat162float(h3));
                size_t o0 = (size_t)row * Nd + col, o1 = (size_t)(row + 8) * Nd + col;
                *(uint32_t*)(Ch + o0) = *reinterpret_cast<uint32_t*>(&p0);
                *(uint32_t*)(Cl + o0) = wl0;
                *(uint32_t*)(Ch + o1) = *reinterpret_cast<uint32_t*>(&p1);
                *(uint32_t*)(Cl + o1) = wl1;
            }
        }
    }
}

// ---------------------------------------------------------------------------
// Tensor-core causal flash attention; consumes pre-split bf16 qkv (q scaled).
// CTA: 64 q-rows x (head, batch); 4 warps; KV double-buffered via cp.async.
// ---------------------------------------------------------------------------
#define APITCH 72                              // bf16/row (144 B)
#define ATILE  9216                            // 64*144
#define AQH 0
#define AQL ATILE
#define AKV0 (2 * ATILE)                       // stage base; KH,KL,VH,VL
#define AKVSTAGE (4 * ATILE)                   // 36864
#define ASMEMB (2 * ATILE + 2 * AKVSTAGE)      // 92160

__global__ __launch_bounds__(128) void attn_mma(
    const __nv_bfloat16* __restrict__ qh, const __nv_bfloat16* __restrict__ ql,
    __nv_bfloat16* __restrict__ zh, __nv_bfloat16* __restrict__ zl)
{
    extern __shared__ __nv_bfloat16 asmem[];
    const uint32_t sb = smem_u32(asmem);
    const int tid = threadIdx.x, lane = tid & 31, wid = tid >> 5;
    const int qb = blockIdx.x, h = blockIdx.y, bb = blockIdx.z;

    const size_t rowbase = (size_t)(bb * SEQ) * QKVN;
    const int hc = h * HDIM;

    const int lr = tid >> 1;
    const int lc4 = (tid & 1) * 4;

    auto load_q = [&] {
#pragma unroll
        for (int j = 0; j < 4; j++) {
            size_t g = rowbase + (size_t)(qb * 64 + lr) * QKVN + hc + (lc4 + j) * 8;
            uint32_t d = (uint32_t)(lr * 144 + (lc4 + j) * 16);
            cp16(sb + AQH + d, qh + g);
            cp16(sb + AQL + d, ql + g);
        }
    };
    auto load_kv = [&](int stage, int kb) {
        uint32_t sbb = sb + AKV0 + stage * AKVSTAGE;
#pragma unroll
        for (int j = 0; j < 4; j++) {
            size_t gk = rowbase + (size_t)(kb * 64 + lr) * QKVN + MODEL + hc + (lc4 + j) * 8;
            size_t gv = gk + MODEL;
            uint32_t d = (uint32_t)(lr * 144 + (lc4 + j) * 16);
            cp16(sbb + d,             qh + gk);
            cp16(sbb + ATILE + d,     ql + gk);
            cp16(sbb + 2 * ATILE + d, qh + gv);
            cp16(sbb + 3 * ATILE + d, ql + gv);
        }
    };

    load_q();
    load_kv(0, 0);
    asm volatile("cp.async.commit_group;" ::: "memory");

    const int arow  = (lane & 7) + ((lane >> 3) & 1) * 8;
    const int acolB = ((lane >> 4) & 1) * 16;
    const int brow  = (lane & 7) + ((lane >> 4) & 1) * 8;
    const int bcolB = ((lane >> 3) & 1) * 16;
    const int vrow  = (lane & 7) + ((lane >> 3) & 1) * 8;
    const int vcol8 = ((lane >> 4) & 1) * 8;

    uint32_t qfh[4][4], qfl[4][4];
    float m0 = -CUDART_INF_F, m1 = -CUDART_INF_F, l0 = 0.f, l1 = 0.f;
    float o[8][4];
#pragma unroll
    for (int i = 0; i < 8; i++)
#pragma unroll
        for (int j = 0; j < 4; j++) o[i][j] = 0.f;

    for (int kb = 0; kb <= qb; kb++) {
        if (kb + 1 <= qb) {
            load_kv((kb + 1) & 1, kb + 1);
            asm volatile("cp.async.commit_group;" ::: "memory");
            asm volatile("cp.async.wait_group 1;" ::: "memory");
        } else {
            asm volatile("cp.async.wait_group 0;" ::: "memory");
        }
        __syncthreads();

        if (kb == 0) {
#pragma unroll
            for (int ks = 0; ks < 4; ks++) {
                uint32_t off = (uint32_t)(wid * 16 + arow) * (APITCH * 2) + ks * 32 + acolB;
                ldm_x4(qfh[ks], sb + AQH + off);
                ldm_x4(qfl[ks], sb + AQL + off);
            }
        }

        const uint32_t kvb = sb + AKV0 + (kb & 1) * AKVSTAGE;
        const uint32_t kh_b = kvb, kl_b = kvb + ATILE;
        const uint32_t vh_b = kvb + 2 * ATILE, vl_b = kvb + 3 * ATILE;

        // ---- S = Q K^T (3-pass split) ----
        float s[8][4];
#pragma unroll
        for (int i = 0; i < 8; i++)
#pragma unroll
            for (int j = 0; j < 4; j++) s[i][j] = 0.f;
#pragma unroll
        for (int ks = 0; ks < 4; ks++) {
#pragma unroll
            for (int np = 0; np < 4; np++) {
                uint32_t off = (uint32_t)(np * 16 + brow) * (APITCH * 2) + ks * 32 + bcolB;
                uint32_t kh4[4], kl4[4];
                ldm_x4(kh4, kh_b + off);
                ldm_x4(kl4, kl_b + off);
                mma16816(s[2*np],   qfh[ks], kh4 + 0);
                mma16816(s[2*np+1], qfh[ks], kh4 + 2);
                mma16816(s[2*np],   qfh[ks], kl4 + 0);
                mma16816(s[2*np+1], qfh[ks], kl4 + 2);
                mma16816(s[2*np],   qfl[ks], kh4 + 0);
                mma16816(s[2*np+1], qfl[ks], kh4 + 2);
            }
        }

        if (kb == qb) {
            const int rr0 = wid * 16 + (lane >> 2);
            const int cc0 = (lane & 3) * 2;
#pragma unroll
            for (int nt = 0; nt < 8; nt++) {
#pragma unroll
                for (int jj = 0; jj < 2; jj++) {
                    int col = nt * 8 + cc0 + jj;
                    if (col > rr0)     s[nt][jj]     = -CUDART_INF_F;
                    if (col > rr0 + 8) s[nt][2 + jj] = -CUDART_INF_F;
                }
            }
        }

        // ---- online softmax ----
        float mx0 = -CUDART_INF_F, mx1 = -CUDART_INF_F;
#pragma unroll
        for (int nt = 0; nt < 8; nt++) {
            mx0 = fmaxf(mx0, fmaxf(s[nt][0], s[nt][1]));
            mx1 = fmaxf(mx1, fmaxf(s[nt][2], s[nt][3]));
        }
        mx0 = fmaxf(mx0, __shfl_xor_sync(0xffffffffu, mx0, 1));
        mx0 = fmaxf(mx0, __shfl_xor_sync(0xffffffffu, mx0, 2));
        mx1 = fmaxf(mx1, __shfl_xor_sync(0xffffffffu, mx1, 1));
        mx1 = fmaxf(mx1, __shfl_xor_sync(0xffffffffu, mx1, 2));
        const float mn0 = fmaxf(m0, mx0), mn1 = fmaxf(m1, mx1);
        const float cr0 = __expf(m0 - mn0), cr1 = __expf(m1 - mn1);
        float sum0 = 0.f, sum1 = 0.f;
        uint32_t pah[4][4], pal[4][4];
#pragma unroll
        for (int kt = 0; kt < 4; kt++) {
#pragma unroll
            for (int hh = 0; hh < 2; hh++) {
                const int nt = 2 * kt + hh;
                float p00 = __expf(s[nt][0] - mn0);
                float p01 = __expf(s[nt][1] - mn0);
                float p10 = __expf(s[nt][2] - mn1);
                float p11 = __expf(s[nt][3] - mn1);
                sum0 += p00 + p01;
                sum1 += p10 + p11;
                __nv_bfloat16 b00 = __float2bfloat16(p00), b01 = __float2bfloat16(p01);
                __nv_bfloat16 b10 = __float2bfloat16(p10), b11 = __float2bfloat16(p11);
                __nv_bfloat162 ph0 = __halves2bfloat162(b00, b01);
                __nv_bfloat162 ph1 = __halves2bfloat162(b10, b11);
                pah[kt][hh * 2 + 0] = *reinterpret_cast<uint32_t*>(&ph0);
                pah[kt][hh * 2 + 1] = *reinterpret_cast<uint32_t*>(&ph1);
                pal[kt][hh * 2 + 0] = packbf(p00 - __bfloat162float(b00),
                                             p01 - __bfloat162float(b01));
                pal[kt][hh * 2 + 1] = packbf(p10 - __bfloat162float(b10),
                                             p11 - __bfloat162float(b11));
            }
        }
        sum0 += __shfl_xor_sync(0xffffffffu, sum0, 1);
        sum0 += __shfl_xor_sync(0xffffffffu, sum0, 2);
        sum1 += __shfl_xor_sync(0xffffffffu, sum1, 1);
        sum1 += __shfl_xor_sync(0xffffffffu, sum1, 2);
        l0 = l0 * cr0 + sum0;  m0 = mn0;
        l1 = l1 * cr1 + sum1;  m1 = mn1;
#pragma unroll
        for (int nt = 0; nt < 8; nt++) {
            o[nt][0] *= cr0; o[nt][1] *= cr0;
            o[nt][2] *= cr1; o[nt][3] *= cr1;
        }

        // ---- O += P V (3-pass split), V via trans ldmatrix ----
#pragma unroll
        for (int kt = 0; kt < 4; kt++) {
#pragma unroll
            for (int p = 0; p < 4; p++) {
                uint32_t off = (uint32_t)(kt * 16 + vrow) * (APITCH * 2)
                             + (uint32_t)(p * 16 + vcol8) * 2;
                uint32_t fvh[4], fvl[4];
                ldm_x4_t(fvh, vh_b + off);
                ldm_x4_t(fvl, vl_b + off);
                mma16816(o[2*p],   pah[kt], fvh + 0);
                mma16816(o[2*p+1], pah[kt], fvh + 2);
                mma16816(o[2*p],   pah[kt], fvl + 0);
                mma16816(o[2*p+1], pah[kt], fvl + 2);
                mma16816(o[2*p],   pal[kt], fvh + 0);
                mma16816(o[2*p+1], pal[kt], fvh + 2);
            }
        }
        __syncthreads();
    }

    // ---- epilogue: normalize, split, store z hi/lo ----
    const float inv0 = 1.f / l0, inv1 = 1.f / l1;
    const int gr0 = bb * SEQ + qb * 64 + wid * 16 + (lane >> 2);
    const int gc  = h * HDIM + (lane & 3) * 2;
#pragma unroll
    for (int nt = 0; nt < 8; nt++) {
        float v0 = o[nt][0] * inv0, v1 = o[nt][1] * inv0;
        float v2 = o[nt][2] * inv1, v3 = o[nt][3] * inv1;
        __nv_bfloat16 h0 = __float2bfloat16(v0), h1 = __float2bfloat16(v1);
        __nv_bfloat16 h2 = __float2bfloat16(v2), h3 = __float2bfloat16(v3);
        __nv_bfloat162 ph0 = __halves2bfloat162(h0, h1);
        __nv_bfloat162 ph1 = __halves2bfloat162(h2, h3);
        uint32_t wl0 = packbf(v0 - __bfloat162float(h0), v1 - __bfloat162float(h1));
        uint32_t wl1 = packbf(v2 - __bfloat162float(h2), v3 - __bfloat162float(h3));
        size_t off0 = (size_t)gr0 * MODEL + gc + nt * 8;
        size_t off1 = (size_t)(gr0 + 8) * MODEL + gc + nt * 8;
        *(uint32_t*)(zh + off0) = *reinterpret_cast<uint32_t*>(&ph0);
        *(uint32_t*)(zl + off0) = wl0;
        *(uint32_t*)(zh + off1) = *reinterpret_cast<uint32_t*>(&ph1);
        *(uint32_t*)(zl + off1) = wl1;
    }
}

// ---------------------------------------------------------------------------
// Launch
// ---------------------------------------------------------------------------
extern "C" void kernel_launch(void* const* d_in, const int* in_sizes, int n_in,
                              void* d_out, int out_size)
{
    const float* x      = (const float*)d_in[0];
    const float* W_attn = (const float*)d_in[1];
    const float* b_attn = (const float*)d_in[2];
    const float* W_proj = (const float*)d_in[3];
    const float* b_proj = (const float*)d_in[4];
    float* out = (float*)d_out;

    __nv_bfloat16 *qh, *ql, *xh, *xl, *wah, *wal, *wph, *wpl, *zh, *zl;
    cudaGetSymbolAddress((void**)&qh,  g_qh);
    cudaGetSymbolAddress((void**)&ql,  g_ql);
    cudaGetSymbolAddress((void**)&xh,  g_xh);
    cudaGetSymbolAddress((void**)&xl,  g_xl);
    cudaGetSymbolAddress((void**)&wah, g_wah);
    cudaGetSymbolAddress((void**)&wal, g_wal);
    cudaGetSymbolAddress((void**)&wph, g_wph);
    cudaGetSymbolAddress((void**)&wpl, g_wpl);
    cudaGetSymbolAddress((void**)&zh,  g_zh);
    cudaGetSymbolAddress((void**)&zl,  g_zl);

    cudaFuncSetAttribute(gemm_mma<0>, cudaFuncAttributeMaxDynamicSharedMemorySize, GSMEM);
    cudaFuncSetAttribute(gemm_mma<1>, cudaFuncAttributeMaxDynamicSharedMemorySize, GSMEM);
    cudaFuncSetAttribute(attn_mma, cudaFuncAttributeMaxDynamicSharedMemorySize, ASMEMB);

    // Prep: split x; transpose+split weights
    split_convert<<<(ROWS * KDIM / 4 + 255) / 256, 256>>>(x, xh, xl, ROWS * KDIM / 4);
    transpose_split<<<dim3(QKVN / 32, KDIM / 32), dim3(32, 8)>>>(W_attn, wah, wal, KDIM, QKVN);
    transpose_split<<<dim3(MODEL / 32, KDIM / 32), dim3(32, 8)>>>(W_proj, wph, wpl, KDIM, MODEL);

    // QKV projection -> split bf16 qkv (q pre-scaled by 1/8)
    gemm_mma<1><<<dim3(QKVN / 128, ROWS / 128), 256, GSMEM>>>(
        xh, xl, wah, wal, b_attn, nullptr, qh, ql, QKVN);

    // causal attention -> z (bf16 hi/lo)
    attn_mma<<<dim3(SEQ / 64, HEADS, BATCH), 128, ASMEMB>>>(qh, ql, zh, zl);

    // output projection -> fp32 out
    gemm_mma<0><<<dim3(MODEL / 128, ROWS / 128), 256, GSMEM>>>(
        zh, zl, wph, wpl, b_proj, out, nullptr, nullptr, MODEL);
}

// round 10
// speedup vs baseline: 1.6602x; 1.6602x over previous
#include <cuda_runtime.h>
#include <cuda_fp16.h>
#include <math_constants.h>
#include <cstdint>

// Problem constants
#define BATCH 2
#define SEQ   2048
#define MODEL 1024
#define HEADS 16
#define HDIM  64
#define ROWS  (BATCH*SEQ)          // 4096
#define QKVN  (3*MODEL)            // 3072
#define KDIM  1024

// ---------------------------------------------------------------------------
// Scratch (device globals: allocation-free)
// ---------------------------------------------------------------------------
__device__ __half g_qh[(size_t)ROWS * QKVN];   // qkv hi (q pre-scaled 1/8)
__device__ __half g_ql[(size_t)ROWS * QKVN];   // qkv lo
__device__ __half g_xh[(size_t)ROWS * KDIM];
__device__ __half g_xl[(size_t)ROWS * KDIM];
__device__ __half g_wah[(size_t)QKVN * KDIM];  // W_attn^T hi only
__device__ __half g_wph[(size_t)MODEL * KDIM]; // W_proj^T hi only
__device__ __half g_zh[(size_t)ROWS * MODEL];
__device__ __half g_zl[(size_t)ROWS * MODEL];

// ---------------------------------------------------------------------------
// Helpers
// ---------------------------------------------------------------------------
__device__ __forceinline__ uint32_t smem_u32(const void* p) {
    uint32_t a;
    asm("{ .reg .u64 t; cvta.to.shared.u64 t, %1; cvt.u32.u64 %0, t; }"
        : "=r"(a) : "l"(p));
    return a;
}
__device__ __forceinline__ void ldm_x4(uint32_t* r, uint32_t a) {
    asm volatile("ldmatrix.sync.aligned.m8n8.x4.shared.b16 {%0,%1,%2,%3}, [%4];"
        : "=r"(r[0]), "=r"(r[1]), "=r"(r[2]), "=r"(r[3]) : "r"(a));
}
__device__ __forceinline__ void ldm_x4_t(uint32_t* r, uint32_t a) {
    asm volatile("ldmatrix.sync.aligned.m8n8.x4.trans.shared.b16 {%0,%1,%2,%3}, [%4];"
        : "=r"(r[0]), "=r"(r[1]), "=r"(r[2]), "=r"(r[3]) : "r"(a));
}
__device__ __forceinline__ void mma16816(float* c, const uint32_t* a, const uint32_t* b) {
    asm volatile("mma.sync.aligned.m16n8k16.row.col.f32.f16.f16.f32 "
        "{%0,%1,%2,%3}, {%4,%5,%6,%7}, {%8,%9}, {%0,%1,%2,%3};"
        : "+f"(c[0]), "+f"(c[1]), "+f"(c[2]), "+f"(c[3])
        : "r"(a[0]), "r"(a[1]), "r"(a[2]), "r"(a[3]), "r"(b[0]), "r"(b[1]));
}
__device__ __forceinline__ void cp16(uint32_t saddr, const void* gaddr) {
    asm volatile("cp.async.cg.shared.global [%0], [%1], 16;" :: "r"(saddr), "l"(gaddr));
}
__device__ __forceinline__ uint32_t packh2(float lo, float hi) {
    __half2 p = __floats2half2_rn(lo, hi);
    return *reinterpret_cast<uint32_t*>(&p);
}
__device__ __forceinline__ void split4(float4 v, uint2& h, uint2& l) {
    __half h0 = __float2half_rn(v.x), h1 = __float2half_rn(v.y);
    __half h2 = __float2half_rn(v.z), h3 = __float2half_rn(v.w);
    h.x = packh2(v.x, v.y); h.y = packh2(v.z, v.w);
    l.x = packh2(v.x - __half2float(h0), v.y - __half2float(h1));
    l.y = packh2(v.z - __half2float(h2), v.w - __half2float(h3));
}

// ---------------------------------------------------------------------------
// Prep kernels
// ---------------------------------------------------------------------------
__global__ void split_convert(const float* __restrict__ x,
                              __half* __restrict__ h,
                              __half* __restrict__ l, int n4)
{
    int i = blockIdx.x * blockDim.x + threadIdx.x;
    if (i >= n4) return;
    float4 v = ((const float4*)x)[i];
    uint2 uh, ul;
    split4(v, uh, ul);
    ((uint2*)h)[i] = uh;
    ((uint2*)l)[i] = ul;
}

// W[K][N] fp32 -> W^T fp16 [N][K] (hi only)
__global__ void transpose_h(const float* __restrict__ W,
                            __half* __restrict__ Th, int Kd, int Nd)
{
    __shared__ float t[32][33];
    int n0 = blockIdx.x * 32, k0 = blockIdx.y * 32;
    int tx = threadIdx.x, ty = threadIdx.y;
#pragma unroll
    for (int j = 0; j < 32; j += 8)
        t[ty + j][tx] = W[(size_t)(k0 + ty + j) * Nd + n0 + tx];
    __syncthreads();
#pragma unroll
    for (int j = 0; j < 32; j += 8) {
        int n = n0 + ty + j, k = k0 + tx;
        Th[(size_t)n * Kd + k] = __float2half_rn(t[tx][ty + j]);
    }
}

// ---------------------------------------------------------------------------
// fp16 2-pass GEMM: C = (Ah+Al) @ Bh^T + bias.
// BK=64, 3 tiles/stage, double-buffered, 2 CTAs/SM.
// MODE 0: C = fp32.  MODE 1: Ch/Cl = fp16 hi/lo of (acc+bias)*(col<MODEL?1/8:1)
// ---------------------------------------------------------------------------
#define GPITCH 144
#define GTILEB (128 * GPITCH)     // 18432
#define GSTAGEB (3 * GTILEB)      // 55296
#define GSMEM  (2 * GSTAGEB)      // 110592

template<int MODE>
__global__ __launch_bounds__(256, 2) void gemm_mma(
    const __half* __restrict__ Ah, const __half* __restrict__ Al,
    const __half* __restrict__ Bh,
    const float* __restrict__ bias, float* __restrict__ C,
    __half* __restrict__ Ch, __half* __restrict__ Cl, int Nd)
{
    extern __shared__ char smem[];
    const uint32_t sbase = smem_u32(smem);
    const int tid  = threadIdx.x;
    const int wid  = tid >> 5, lane = tid & 31;
    const int bn   = blockIdx.x * 128;
    const int bm   = blockIdx.y * 128;
    const int wm0  = (wid & 3) * 32;
    const int wn0  = (wid >> 2) * 64;

    const int lrow = tid >> 3;        // 0..31
    const int lc   = tid & 7;         // 16B chunk

    const __half* srcA_h = Ah + (size_t)(bm + lrow) * KDIM + lc * 8;
    const __half* srcA_l = Al + (size_t)(bm + lrow) * KDIM + lc * 8;
    const __half* srcB_h = Bh + (size_t)(bn + lrow) * KDIM + lc * 8;

    const int arow  = (lane & 7) + ((lane >> 3) & 1) * 8;
    const int acolB = ((lane >> 4) & 1) * 16;
    const int brow  = (lane & 7) + ((lane >> 4) & 1) * 8;
    const int bcolB = ((lane >> 3) & 1) * 16;

    float acc[16][4];
#pragma unroll
    for (int i = 0; i < 16; i++)
#pragma unroll
        for (int j = 0; j < 4; j++) acc[i][j] = 0.f;

    auto issue = [&](int stage, int k0) {
        uint32_t so = sbase + stage * GSTAGEB + lrow * GPITCH + lc * 16;
#pragma unroll
        for (int i = 0; i < 4; i++) {
            uint32_t sa = so + i * 32 * GPITCH;
            size_t   go = (size_t)i * 32 * KDIM + k0;
            cp16(sa,              srcA_h + go);
            cp16(sa + GTILEB,     srcA_l + go);
            cp16(sa + 2 * GTILEB, srcB_h + go);
        }
        asm volatile("cp.async.commit_group;" ::: "memory");
    };

    issue(0, 0);

    for (int c = 0; c < 16; c++) {
        if (c + 1 < 16) {
            issue((c + 1) & 1, (c + 1) * 64);
            asm volatile("cp.async.wait_group 1;" ::: "memory");
        } else {
            asm volatile("cp.async.wait_group 0;" ::: "memory");
        }
        __syncthreads();

        const uint32_t ab  = sbase + (c & 1) * GSTAGEB;
        const uint32_t alb = ab + GTILEB;
        const uint32_t bb  = ab + 2 * GTILEB;

#pragma unroll
        for (int ks = 0; ks < 4; ks++) {
            uint32_t fah[2][4], fal[2][4], fbh[4][4];
#pragma unroll
            for (int ma = 0; ma < 2; ma++) {
                uint32_t off = (uint32_t)(wm0 + ma * 16 + arow) * GPITCH + ks * 32 + acolB;
                ldm_x4(fah[ma], ab + off);
                ldm_x4(fal[ma], alb + off);
            }
#pragma unroll
            for (int na = 0; na < 4; na++) {
                uint32_t off = (uint32_t)(wn0 + na * 16 + brow) * GPITCH + ks * 32 + bcolB;
                ldm_x4(fbh[na], bb + off);
            }
#pragma unroll
            for (int ma = 0; ma < 2; ma++) {
#pragma unroll
                for (int na = 0; na < 4; na++) {
                    float* c0 = acc[ma * 8 + na * 2];
                    float* c1 = acc[ma * 8 + na * 2 + 1];
                    mma16816(c0, fah[ma], fbh[na]);
                    mma16816(c1, fah[ma], fbh[na] + 2);
                    mma16816(c0, fal[ma], fbh[na]);
                    mma16816(c1, fal[ma], fbh[na] + 2);
                }
            }
        }
        __syncthreads();
    }

    const int er = bm + wm0 + (lane >> 2);
    const int ec = bn + wn0 + (lane & 3) * 2;
#pragma unroll
    for (int ma = 0; ma < 2; ma++) {
#pragma unroll
        for (int na = 0; na < 8; na++) {
            const float* a4 = acc[ma * 8 + na];
            int row = er + ma * 16;
            int col = ec + na * 8;
            float b0 = __ldg(bias + col), b1 = __ldg(bias + col + 1);
            if (MODE == 0) {
                float2 v0 = make_float2(a4[0] + b0, a4[1] + b1);
                float2 v1 = make_float2(a4[2] + b0, a4[3] + b1);
                *(float2*)(C + (size_t)row * Nd + col)       = v0;
                *(float2*)(C + (size_t)(row + 8) * Nd + col) = v1;
            } else {
                float sc = (col < MODEL) ? 0.125f : 1.f;
                float v0 = (a4[0] + b0) * sc, v1 = (a4[1] + b1) * sc;
                float v2 = (a4[2] + b0) * sc, v3 = (a4[3] + b1) * sc;
                __half h0 = __float2half_rn(v0), h1 = __float2half_rn(v1);
                __half h2 = __float2half_rn(v2), h3 = __float2half_rn(v3);
                size_t o0 = (size_t)row * Nd + col, o1 = (size_t)(row + 8) * Nd + col;
                *(uint32_t*)(Ch + o0) = packh2(v0, v1);
                *(uint32_t*)(Cl + o0) = packh2(v0 - __half2float(h0), v1 - __half2float(h1));
                *(uint32_t*)(Ch + o1) = packh2(v2, v3);
                *(uint32_t*)(Cl + o1) = packh2(v2 - __half2float(h2), v3 - __half2float(h3));
            }
        }
    }
}

// ---------------------------------------------------------------------------
// fp16 2-pass causal flash attention. Q split hi/lo; K,V hi-only.
// CTA: 64 q-rows x (head, batch); 4 warps; KV double-buffered via cp.async.
// ---------------------------------------------------------------------------
#define APITCH 72                              // fp16/row (144 B)
#define ATILE  9216                            // 64*144
#define AQH 0
#define AQL ATILE
#define AKV0 (2 * ATILE)                       // stage: {Kh, Vh}
#define AKVSTAGE (2 * ATILE)                   // 18432
#define ASMEMB (2 * ATILE + 2 * AKVSTAGE)      // 55296

__global__ __launch_bounds__(128) void attn_mma(
    const __half* __restrict__ qh, const __half* __restrict__ ql,
    __half* __restrict__ zh, __half* __restrict__ zl)
{
    extern __shared__ __half asmem[];
    const uint32_t sb = smem_u32(asmem);
    const int tid = threadIdx.x, lane = tid & 31, wid = tid >> 5;
    const int qb = blockIdx.x, h = blockIdx.y, bb = blockIdx.z;

    const size_t rowbase = (size_t)(bb * SEQ) * QKVN;
    const int hc = h * HDIM;

    const int lr = tid >> 1;
    const int lc4 = (tid & 1) * 4;

    auto load_q = [&] {
#pragma unroll
        for (int j = 0; j < 4; j++) {
            size_t g = rowbase + (size_t)(qb * 64 + lr) * QKVN + hc + (lc4 + j) * 8;
            uint32_t d = (uint32_t)(lr * 144 + (lc4 + j) * 16);
            cp16(sb + AQH + d, qh + g);
            cp16(sb + AQL + d, ql + g);
        }
    };
    auto load_kv = [&](int stage, int kb) {
        uint32_t sbb = sb + AKV0 + stage * AKVSTAGE;
#pragma unroll
        for (int j = 0; j < 4; j++) {
            size_t gk = rowbase + (size_t)(kb * 64 + lr) * QKVN + MODEL + hc + (lc4 + j) * 8;
            uint32_t d = (uint32_t)(lr * 144 + (lc4 + j) * 16);
            cp16(sbb + d,         qh + gk);           // K hi
            cp16(sbb + ATILE + d, qh + gk + MODEL);   // V hi
        }
    };

    load_q();
    load_kv(0, 0);
    asm volatile("cp.async.commit_group;" ::: "memory");

    const int arow  = (lane & 7) + ((lane >> 3) & 1) * 8;
    const int acolB = ((lane >> 4) & 1) * 16;
    const int brow  = (lane & 7) + ((lane >> 4) & 1) * 8;
    const int bcolB = ((lane >> 3) & 1) * 16;
    const int vrow  = (lane & 7) + ((lane >> 3) & 1) * 8;
    const int vcol8 = ((lane >> 4) & 1) * 8;

    uint32_t qfh[4][4], qfl[4][4];
    float m0 = -CUDART_INF_F, m1 = -CUDART_INF_F, l0 = 0.f, l1 = 0.f;
    float o[8][4];
#pragma unroll
    for (int i = 0; i < 8; i++)
#pragma unroll
        for (int j = 0; j < 4; j++) o[i][j] = 0.f;

    for (int kb = 0; kb <= qb; kb++) {
        if (kb + 1 <= qb) {
            load_kv((kb + 1) & 1, kb + 1);
            asm volatile("cp.async.commit_group;" ::: "memory");
            asm volatile("cp.async.wait_group 1;" ::: "memory");
        } else {
            asm volatile("cp.async.wait_group 0;" ::: "memory");
        }
        __syncthreads();

        if (kb == 0) {
#pragma unroll
            for (int ks = 0; ks < 4; ks++) {
                uint32_t off = (uint32_t)(wid * 16 + arow) * (APITCH * 2) + ks * 32 + acolB;
                ldm_x4(qfh[ks], sb + AQH + off);
                ldm_x4(qfl[ks], sb + AQL + off);
            }
        }

        const uint32_t kvb = sb + AKV0 + (kb & 1) * AKVSTAGE;
        const uint32_t kh_b = kvb;
        const uint32_t vh_b = kvb + ATILE;

        // ---- S = Q K^T (2-pass) ----
        float s[8][4];
#pragma unroll
        for (int i = 0; i < 8; i++)
#pragma unroll
            for (int j = 0; j < 4; j++) s[i][j] = 0.f;
#pragma unroll
        for (int ks = 0; ks < 4; ks++) {
#pragma unroll
            for (int np = 0; np < 4; np++) {
                uint32_t off = (uint32_t)(np * 16 + brow) * (APITCH * 2) + ks * 32 + bcolB;
                uint32_t kh4[4];
                ldm_x4(kh4, kh_b + off);
                mma16816(s[2*np],   qfh[ks], kh4 + 0);
                mma16816(s[2*np+1], qfh[ks], kh4 + 2);
                mma16816(s[2*np],   qfl[ks], kh4 + 0);
                mma16816(s[2*np+1], qfl[ks], kh4 + 2);
            }
        }

        if (kb == qb) {
            const int rr0 = wid * 16 + (lane >> 2);
            const int cc0 = (lane & 3) * 2;
#pragma unroll
            for (int nt = 0; nt < 8; nt++) {
#pragma unroll
                for (int jj = 0; jj < 2; jj++) {
                    int col = nt * 8 + cc0 + jj;
                    if (col > rr0)     s[nt][jj]     = -CUDART_INF_F;
                    if (col > rr0 + 8) s[nt][2 + jj] = -CUDART_INF_F;
                }
            }
        }

        // ---- online softmax ----
        float mx0 = -CUDART_INF_F, mx1 = -CUDART_INF_F;
#pragma unroll
        for (int nt = 0; nt < 8; nt++) {
            mx0 = fmaxf(mx0, fmaxf(s[nt][0], s[nt][1]));
            mx1 = fmaxf(mx1, fmaxf(s[nt][2], s[nt][3]));
        }
        mx0 = fmaxf(mx0, __shfl_xor_sync(0xffffffffu, mx0, 1));
        mx0 = fmaxf(mx0, __shfl_xor_sync(0xffffffffu, mx0, 2));
        mx1 = fmaxf(mx1, __shfl_xor_sync(0xffffffffu, mx1, 1));
        mx1 = fmaxf(mx1, __shfl_xor_sync(0xffffffffu, mx1, 2));
        const float mn0 = fmaxf(m0, mx0), mn1 = fmaxf(m1, mx1);
        const float cr0 = __expf(m0 - mn0), cr1 = __expf(m1 - mn1);
        float sum0 = 0.f, sum1 = 0.f;
        uint32_t pah[4][4], pal[4][4];
#pragma unroll
        for (int kt = 0; kt < 4; kt++) {
#pragma unroll
            for (int hh = 0; hh < 2; hh++) {
                const int nt = 2 * kt + hh;
                float p00 = __expf(s[nt][0] - mn0);
                float p01 = __expf(s[nt][1] - mn0);
                float p10 = __expf(s[nt][2] - mn1);
                float p11 = __expf(s[nt][3] - mn1);
                sum0 += p00 + p01;
                sum1 += p10 + p11;
                __half b00 = __float2half_rn(p00), b01 = __float2half_rn(p01);
                __half b10 = __float2half_rn(p10), b11 = __float2half_rn(p11);
                pah[kt][hh * 2 + 0] = packh2(p00, p01);
                pah[kt][hh * 2 + 1] = packh2(p10, p11);
                pal[kt][hh * 2 + 0] = packh2(p00 - __half2float(b00),
                                             p01 - __half2float(b01));
                pal[kt][hh * 2 + 1] = packh2(p10 - __half2float(b10),
                                             p11 - __half2float(b11));
            }
        }
        sum0 += __shfl_xor_sync(0xffffffffu, sum0, 1);
        sum0 += __shfl_xor_sync(0xffffffffu, sum0, 2);
        sum1 += __shfl_xor_sync(0xffffffffu, sum1, 1);
        sum1 += __shfl_xor_sync(0xffffffffu, sum1, 2);
        l0 = l0 * cr0 + sum0;  m0 = mn0;
        l1 = l1 * cr1 + sum1;  m1 = mn1;
#pragma unroll
        for (int nt = 0; nt < 8; nt++) {
            o[nt][0] *= cr0; o[nt][1] *= cr0;
            o[nt][2] *= cr1; o[nt][3] *= cr1;
        }

        // ---- O += P V (2-pass), V via trans ldmatrix ----
#pragma unroll
        for (int kt = 0; kt < 4; kt++) {
#pragma unroll
            for (int p = 0; p < 4; p++) {
                uint32_t off = (uint32_t)(kt * 16 + vrow) * (APITCH * 2)
                             + (uint32_t)(p * 16 + vcol8) * 2;
                uint32_t fvh[4];
                ldm_x4_t(fvh, vh_b + off);
                mma16816(o[2*p],   pah[kt], fvh + 0);
                mma16816(o[2*p+1], pah[kt], fvh + 2);
                mma16816(o[2*p],   pal[kt], fvh + 0);
                mma16816(o[2*p+1], pal[kt], fvh + 2);
            }
        }
        __syncthreads();
    }

    // ---- epilogue: normalize, split, store z hi/lo ----
    const float inv0 = 1.f / l0, inv1 = 1.f / l1;
    const int gr0 = bb * SEQ + qb * 64 + wid * 16 + (lane >> 2);
    const int gc  = h * HDIM + (lane & 3) * 2;
#pragma unroll
    for (int nt = 0; nt < 8; nt++) {
        float v0 = o[nt][0] * inv0, v1 = o[nt][1] * inv0;
        float v2 = o[nt][2] * inv1, v3 = o[nt][3] * inv1;
        __half h0 = __float2half_rn(v0), h1 = __float2half_rn(v1);
        __half h2 = __float2half_rn(v2), h3 = __float2half_rn(v3);
        size_t off0 = (size_t)gr0 * MODEL + gc + nt * 8;
        size_t off1 = (size_t)(gr0 + 8) * MODEL + gc + nt * 8;
        *(uint32_t*)(zh + off0) = packh2(v0, v1);
        *(uint32_t*)(zl + off0) = packh2(v0 - __half2float(h0), v1 - __half2float(h1));
        *(uint32_t*)(zh + off1) = packh2(v2, v3);
        *(uint32_t*)(zl + off1) = packh2(v2 - __half2float(h2), v3 - __half2float(h3));
    }
}

// ---------------------------------------------------------------------------
// Launch
// ---------------------------------------------------------------------------
extern "C" void kernel_launch(void* const* d_in, const int* in_sizes, int n_in,
                              void* d_out, int out_size)
{
    const float* x      = (const float*)d_in[0];
    const float* W_attn = (const float*)d_in[1];
    const float* b_attn = (const float*)d_in[2];
    const float* W_proj = (const float*)d_in[3];
    const float* b_proj = (const float*)d_in[4];
    float* out = (float*)d_out;

    __half *qh, *ql, *xh, *xl, *wah, *wph, *zh, *zl;
    cudaGetSymbolAddress((void**)&qh,  g_qh);
    cudaGetSymbolAddress((void**)&ql,  g_ql);
    cudaGetSymbolAddress((void**)&xh,  g_xh);
    cudaGetSymbolAddress((void**)&xl,  g_xl);
    cudaGetSymbolAddress((void**)&wah, g_wah);
    cudaGetSymbolAddress((void**)&wph, g_wph);
    cudaGetSymbolAddress((void**)&zh,  g_zh);
    cudaGetSymbolAddress((void**)&zl,  g_zl);

    cudaFuncSetAttribute(gemm_mma<0>, cudaFuncAttributeMaxDynamicSharedMemorySize, GSMEM);
    cudaFuncSetAttribute(gemm_mma<1>, cudaFuncAttributeMaxDynamicSharedMemorySize, GSMEM);
    cudaFuncSetAttribute(attn_mma, cudaFuncAttributeMaxDynamicSharedMemorySize, ASMEMB);

    // Prep: split x (hi/lo); transpose weights (hi only)
    split_convert<<<(ROWS * KDIM / 4 + 255) / 256, 256>>>(x, xh, xl, ROWS * KDIM / 4);
    transpose_h<<<dim3(QKVN / 32, KDIM / 32), dim3(32, 8)>>>(W_attn, wah, KDIM, QKVN);
    transpose_h<<<dim3(MODEL / 32, KDIM / 32), dim3(32, 8)>>>(W_proj, wph, KDIM, MODEL);

    // QKV projection -> split fp16 qkv (q pre-scaled by 1/8)
    gemm_mma<1><<<dim3(QKVN / 128, ROWS / 128), 256, GSMEM>>>(
        xh, xl, wah, b_attn, nullptr, qh, ql, QKVN);

    // causal attention -> z (fp16 hi/lo)
    attn_mma<<<dim3(SEQ / 64, HEADS, BATCH), 128, ASMEMB>>>(qh, ql, zh, zl);

    // output projection -> fp32 out
    gemm_mma<0><<<dim3(MODEL / 128, ROWS / 128), 256, GSMEM>>>(
        zh, zl, wph, b_proj, out, nullptr, nullptr, MODEL);
}

// round 11
// speedup vs baseline: 1.8989x; 1.1438x over previous
#include <cuda_runtime.h>
#include <cuda_fp16.h>
#include <math_constants.h>
#include <cstdint>

// Problem constants
#define BATCH 2
#define SEQ   2048
#define MODEL 1024
#define HEADS 16
#define HDIM  64
#define ROWS  (BATCH*SEQ)          // 4096
#define QKVN  (3*MODEL)            // 3072
#define KDIM  1024

// ---------------------------------------------------------------------------
// Scratch (device globals: allocation-free)
// ---------------------------------------------------------------------------
__device__ __half g_qh[(size_t)ROWS * QKVN];   // qkv hi (q pre-scaled 1/8)
__device__ __half g_ql[(size_t)ROWS * QKVN];   // qkv lo
__device__ __half g_xh[(size_t)ROWS * KDIM];
__device__ __half g_xl[(size_t)ROWS * KDIM];
__device__ __half g_wah[(size_t)QKVN * KDIM];  // W_attn^T hi only
__device__ __half g_wph[(size_t)MODEL * KDIM]; // W_proj^T hi only
__device__ __half g_zh[(size_t)ROWS * MODEL];  // z hi only (single-pass GEMM2)

// ---------------------------------------------------------------------------
// Helpers
// ---------------------------------------------------------------------------
__device__ __forceinline__ uint32_t smem_u32(const void* p) {
    uint32_t a;
    asm("{ .reg .u64 t; cvta.to.shared.u64 t, %1; cvt.u32.u64 %0, t; }"
        : "=r"(a) : "l"(p));
    return a;
}
__device__ __forceinline__ void ldm_x4(uint32_t* r, uint32_t a) {
    asm volatile("ldmatrix.sync.aligned.m8n8.x4.shared.b16 {%0,%1,%2,%3}, [%4];"
        : "=r"(r[0]), "=r"(r[1]), "=r"(r[2]), "=r"(r[3]) : "r"(a));
}
__device__ __forceinline__ void ldm_x4_t(uint32_t* r, uint32_t a) {
    asm volatile("ldmatrix.sync.aligned.m8n8.x4.trans.shared.b16 {%0,%1,%2,%3}, [%4];"
        : "=r"(r[0]), "=r"(r[1]), "=r"(r[2]), "=r"(r[3]) : "r"(a));
}
__device__ __forceinline__ void mma16816(float* c, const uint32_t* a, const uint32_t* b) {
    asm volatile("mma.sync.aligned.m16n8k16.row.col.f32.f16.f16.f32 "
        "{%0,%1,%2,%3}, {%4,%5,%6,%7}, {%8,%9}, {%0,%1,%2,%3};"
        : "+f"(c[0]), "+f"(c[1]), "+f"(c[2]), "+f"(c[3])
        : "r"(a[0]), "r"(a[1]), "r"(a[2]), "r"(a[3]), "r"(b[0]), "r"(b[1]));
}
__device__ __forceinline__ void cp16(uint32_t saddr, const void* gaddr) {
    asm volatile("cp.async.cg.shared.global [%0], [%1], 16;" :: "r"(saddr), "l"(gaddr));
}
__device__ __forceinline__ uint32_t packh2(float lo, float hi) {
    __half2 p = __floats2half2_rn(lo, hi);
    return *reinterpret_cast<uint32_t*>(&p);
}
__device__ __forceinline__ void split4(float4 v, uint2& h, uint2& l) {
    __half h0 = __float2half_rn(v.x), h1 = __float2half_rn(v.y);
    __half h2 = __float2half_rn(v.z), h3 = __float2half_rn(v.w);
    h.x = packh2(v.x, v.y); h.y = packh2(v.z, v.w);
    l.x = packh2(v.x - __half2float(h0), v.y - __half2float(h1));
    l.y = packh2(v.z - __half2float(h2), v.w - __half2float(h3));
}

// ---------------------------------------------------------------------------
// Prep kernels
// ---------------------------------------------------------------------------
__global__ void split_convert(const float* __restrict__ x,
                              __half* __restrict__ h,
                              __half* __restrict__ l, int n4)
{
    int i = blockIdx.x * blockDim.x + threadIdx.x;
    if (i >= n4) return;
    float4 v = ((const float4*)x)[i];
    uint2 uh, ul;
    split4(v, uh, ul);
    ((uint2*)h)[i] = uh;
    ((uint2*)l)[i] = ul;
}

// W[K][N] fp32 -> W^T fp16 [N][K] (hi only)
__global__ void transpose_h(const float* __restrict__ W,
                            __half* __restrict__ Th, int Kd, int Nd)
{
    __shared__ float t[32][33];
    int n0 = blockIdx.x * 32, k0 = blockIdx.y * 32;
    int tx = threadIdx.x, ty = threadIdx.y;
#pragma unroll
    for (int j = 0; j < 32; j += 8)
        t[ty + j][tx] = W[(size_t)(k0 + ty + j) * Nd + n0 + tx];
    __syncthreads();
#pragma unroll
    for (int j = 0; j < 32; j += 8) {
        int n = n0 + ty + j, k = k0 + tx;
        Th[(size_t)n * Kd + k] = __float2half_rn(t[tx][ty + j]);
    }
}

// ---------------------------------------------------------------------------
// fp16 GEMM. PASSES=2: C = (Ah+Al) @ Bh^T + bias;  PASSES=1: C = Ah @ Bh^T + bias.
// BK=64, 3 tiles/stage layout, double-buffered, 2 CTAs/SM.
// MODE 0: C = fp32.  MODE 1: Ch/Cl = fp16 hi/lo of (acc+bias)*(col<MODEL?1/8:1)
// ---------------------------------------------------------------------------
#define GPITCH 144
#define GTILEB (128 * GPITCH)     // 18432
#define GSTAGEB (3 * GTILEB)      // 55296
#define GSMEM  (2 * GSTAGEB)      // 110592

template<int MODE, int PASSES>
__global__ __launch_bounds__(256, 2) void gemm_mma(
    const __half* __restrict__ Ah, const __half* __restrict__ Al,
    const __half* __restrict__ Bh,
    const float* __restrict__ bias, float* __restrict__ C,
    __half* __restrict__ Ch, __half* __restrict__ Cl, int Nd)
{
    extern __shared__ char smem[];
    const uint32_t sbase = smem_u32(smem);
    const int tid  = threadIdx.x;
    const int wid  = tid >> 5, lane = tid & 31;
    const int bn   = blockIdx.x * 128;
    const int bm   = blockIdx.y * 128;
    const int wm0  = (wid & 3) * 32;
    const int wn0  = (wid >> 2) * 64;

    const int lrow = tid >> 3;        // 0..31
    const int lc   = tid & 7;         // 16B chunk

    const __half* srcA_h = Ah + (size_t)(bm + lrow) * KDIM + lc * 8;
    const __half* srcA_l = (PASSES == 2) ? (Al + (size_t)(bm + lrow) * KDIM + lc * 8) : nullptr;
    const __half* srcB_h = Bh + (size_t)(bn + lrow) * KDIM + lc * 8;

    const int arow  = (lane & 7) + ((lane >> 3) & 1) * 8;
    const int acolB = ((lane >> 4) & 1) * 16;
    const int brow  = (lane & 7) + ((lane >> 4) & 1) * 8;
    const int bcolB = ((lane >> 3) & 1) * 16;

    float acc[16][4];
#pragma unroll
    for (int i = 0; i < 16; i++)
#pragma unroll
        for (int j = 0; j < 4; j++) acc[i][j] = 0.f;

    auto issue = [&](int stage, int k0) {
        uint32_t so = sbase + stage * GSTAGEB + lrow * GPITCH + lc * 16;
#pragma unroll
        for (int i = 0; i < 4; i++) {
            uint32_t sa = so + i * 32 * GPITCH;
            size_t   go = (size_t)i * 32 * KDIM + k0;
            cp16(sa,              srcA_h + go);
            if (PASSES == 2) cp16(sa + GTILEB, srcA_l + go);
            cp16(sa + 2 * GTILEB, srcB_h + go);
        }
        asm volatile("cp.async.commit_group;" ::: "memory");
    };

    issue(0, 0);

    for (int c = 0; c < 16; c++) {
        if (c + 1 < 16) {
            issue((c + 1) & 1, (c + 1) * 64);
            asm volatile("cp.async.wait_group 1;" ::: "memory");
        } else {
            asm volatile("cp.async.wait_group 0;" ::: "memory");
        }
        __syncthreads();

        const uint32_t ab  = sbase + (c & 1) * GSTAGEB;
        const uint32_t alb = ab + GTILEB;
        const uint32_t bb  = ab + 2 * GTILEB;

#pragma unroll
        for (int ks = 0; ks < 4; ks++) {
            uint32_t fah[2][4], fal[2][4], fbh[4][4];
#pragma unroll
            for (int ma = 0; ma < 2; ma++) {
                uint32_t off = (uint32_t)(wm0 + ma * 16 + arow) * GPITCH + ks * 32 + acolB;
                ldm_x4(fah[ma], ab + off);
                if (PASSES == 2) ldm_x4(fal[ma], alb + off);
            }
#pragma unroll
            for (int na = 0; na < 4; na++) {
                uint32_t off = (uint32_t)(wn0 + na * 16 + brow) * GPITCH + ks * 32 + bcolB;
                ldm_x4(fbh[na], bb + off);
            }
#pragma unroll
            for (int ma = 0; ma < 2; ma++) {
#pragma unroll
                for (int na = 0; na < 4; na++) {
                    float* c0 = acc[ma * 8 + na * 2];
                    float* c1 = acc[ma * 8 + na * 2 + 1];
                    mma16816(c0, fah[ma], fbh[na]);
                    mma16816(c1, fah[ma], fbh[na] + 2);
                    if (PASSES == 2) {
                        mma16816(c0, fal[ma], fbh[na]);
                        mma16816(c1, fal[ma], fbh[na] + 2);
                    }
                }
            }
        }
        __syncthreads();
    }

    const int er = bm + wm0 + (lane >> 2);
    const int ec = bn + wn0 + (lane & 3) * 2;
#pragma unroll
    for (int ma = 0; ma < 2; ma++) {
#pragma unroll
        for (int na = 0; na < 8; na++) {
            const float* a4 = acc[ma * 8 + na];
            int row = er + ma * 16;
            int col = ec + na * 8;
            float b0 = __ldg(bias + col), b1 = __ldg(bias + col + 1);
            if (MODE == 0) {
                float2 v0 = make_float2(a4[0] + b0, a4[1] + b1);
                float2 v1 = make_float2(a4[2] + b0, a4[3] + b1);
                *(float2*)(C + (size_t)row * Nd + col)       = v0;
                *(float2*)(C + (size_t)(row + 8) * Nd + col) = v1;
            } else {
                float sc = (col < MODEL) ? 0.125f : 1.f;
                float v0 = (a4[0] + b0) * sc, v1 = (a4[1] + b1) * sc;
                float v2 = (a4[2] + b0) * sc, v3 = (a4[3] + b1) * sc;
                __half h0 = __float2half_rn(v0), h1 = __float2half_rn(v1);
                __half h2 = __float2half_rn(v2), h3 = __float2half_rn(v3);
                size_t o0 = (size_t)row * Nd + col, o1 = (size_t)(row + 8) * Nd + col;
                *(uint32_t*)(Ch + o0) = packh2(v0, v1);
                *(uint32_t*)(Cl + o0) = packh2(v0 - __half2float(h0), v1 - __half2float(h1));
                *(uint32_t*)(Ch + o1) = packh2(v2, v3);
                *(uint32_t*)(Cl + o1) = packh2(v2 - __half2float(h2), v3 - __half2float(h3));
            }
        }
    }
}

// ---------------------------------------------------------------------------
// fp16 causal flash attention. QK^T: 2-pass (Q hi/lo, K hi). PV: 1-pass (P,V hi).
// CTA: 64 q-rows x (head, batch); heavy q-tiles scheduled FIRST (qb reversed).
// KV double-buffered via cp.async. Outputs z hi only.
// ---------------------------------------------------------------------------
#define APITCH 72                              // fp16/row (144 B)
#define ATILE  9216                            // 64*144
#define AQH 0
#define AQL ATILE
#define AKV0 (2 * ATILE)                       // stage: {Kh, Vh}
#define AKVSTAGE (2 * ATILE)                   // 18432
#define ASMEMB (2 * ATILE + 2 * AKVSTAGE)      // 55296

__global__ __launch_bounds__(128) void attn_mma(
    const __half* __restrict__ qh, const __half* __restrict__ ql,
    __half* __restrict__ zh)
{
    extern __shared__ __half asmem[];
    const uint32_t sb = smem_u32(asmem);
    const int tid = threadIdx.x, lane = tid & 31, wid = tid >> 5;
    const int qb = gridDim.x - 1 - blockIdx.x;   // heavy tiles first
    const int h = blockIdx.y, bb = blockIdx.z;

    const size_t rowbase = (size_t)(bb * SEQ) * QKVN;
    const int hc = h * HDIM;

    const int lr = tid >> 1;
    const int lc4 = (tid & 1) * 4;

    auto load_q = [&] {
#pragma unroll
        for (int j = 0; j < 4; j++) {
            size_t g = rowbase + (size_t)(qb * 64 + lr) * QKVN + hc + (lc4 + j) * 8;
            uint32_t d = (uint32_t)(lr * 144 + (lc4 + j) * 16);
            cp16(sb + AQH + d, qh + g);
            cp16(sb + AQL + d, ql + g);
        }
    };
    auto load_kv = [&](int stage, int kb) {
        uint32_t sbb = sb + AKV0 + stage * AKVSTAGE;
#pragma unroll
        for (int j = 0; j < 4; j++) {
            size_t gk = rowbase + (size_t)(kb * 64 + lr) * QKVN + MODEL + hc + (lc4 + j) * 8;
            uint32_t d = (uint32_t)(lr * 144 + (lc4 + j) * 16);
            cp16(sbb + d,         qh + gk);           // K hi
            cp16(sbb + ATILE + d, qh + gk + MODEL);   // V hi
        }
    };

    load_q();
    load_kv(0, 0);
    asm volatile("cp.async.commit_group;" ::: "memory");

    const int arow  = (lane & 7) + ((lane >> 3) & 1) * 8;
    const int acolB = ((lane >> 4) & 1) * 16;
    const int brow  = (lane & 7) + ((lane >> 4) & 1) * 8;
    const int bcolB = ((lane >> 3) & 1) * 16;
    const int vrow  = (lane & 7) + ((lane >> 3) & 1) * 8;
    const int vcol8 = ((lane >> 4) & 1) * 8;

    uint32_t qfh[4][4], qfl[4][4];
    float m0 = -CUDART_INF_F, m1 = -CUDART_INF_F, l0 = 0.f, l1 = 0.f;
    float o[8][4];
#pragma unroll
    for (int i = 0; i < 8; i++)
#pragma unroll
        for (int j = 0; j < 4; j++) o[i][j] = 0.f;

    for (int kb = 0; kb <= qb; kb++) {
        if (kb + 1 <= qb) {
            load_kv((kb + 1) & 1, kb + 1);
            asm volatile("cp.async.commit_group;" ::: "memory");
            asm volatile("cp.async.wait_group 1;" ::: "memory");
        } else {
            asm volatile("cp.async.wait_group 0;" ::: "memory");
        }
        __syncthreads();

        if (kb == 0) {
#pragma unroll
            for (int ks = 0; ks < 4; ks++) {
                uint32_t off = (uint32_t)(wid * 16 + arow) * (APITCH * 2) + ks * 32 + acolB;
                ldm_x4(qfh[ks], sb + AQH + off);
                ldm_x4(qfl[ks], sb + AQL + off);
            }
        }

        const uint32_t kvb = sb + AKV0 + (kb & 1) * AKVSTAGE;
        const uint32_t kh_b = kvb;
        const uint32_t vh_b = kvb + ATILE;

        // ---- S = Q K^T (2-pass) ----
        float s[8][4];
#pragma unroll
        for (int i = 0; i < 8; i++)
#pragma unroll
            for (int j = 0; j < 4; j++) s[i][j] = 0.f;
#pragma unroll
        for (int ks = 0; ks < 4; ks++) {
#pragma unroll
            for (int np = 0; np < 4; np++) {
                uint32_t off = (uint32_t)(np * 16 + brow) * (APITCH * 2) + ks * 32 + bcolB;
                uint32_t kh4[4];
                ldm_x4(kh4, kh_b + off);
                mma16816(s[2*np],   qfh[ks], kh4 + 0);
                mma16816(s[2*np+1], qfh[ks], kh4 + 2);
                mma16816(s[2*np],   qfl[ks], kh4 + 0);
                mma16816(s[2*np+1], qfl[ks], kh4 + 2);
            }
        }

        if (kb == qb) {
            const int rr0 = wid * 16 + (lane >> 2);
            const int cc0 = (lane & 3) * 2;
#pragma unroll
            for (int nt = 0; nt < 8; nt++) {
#pragma unroll
                for (int jj = 0; jj < 2; jj++) {
                    int col = nt * 8 + cc0 + jj;
                    if (col > rr0)     s[nt][jj]     = -CUDART_INF_F;
                    if (col > rr0 + 8) s[nt][2 + jj] = -CUDART_INF_F;
                }
            }
        }

        // ---- online softmax ----
        float mx0 = -CUDART_INF_F, mx1 = -CUDART_INF_F;
#pragma unroll
        for (int nt = 0; nt < 8; nt++) {
            mx0 = fmaxf(mx0, fmaxf(s[nt][0], s[nt][1]));
            mx1 = fmaxf(mx1, fmaxf(s[nt][2], s[nt][3]));
        }
        mx0 = fmaxf(mx0, __shfl_xor_sync(0xffffffffu, mx0, 1));
        mx0 = fmaxf(mx0, __shfl_xor_sync(0xffffffffu, mx0, 2));
        mx1 = fmaxf(mx1, __shfl_xor_sync(0xffffffffu, mx1, 1));
        mx1 = fmaxf(mx1, __shfl_xor_sync(0xffffffffu, mx1, 2));
        const float mn0 = fmaxf(m0, mx0), mn1 = fmaxf(m1, mx1);
        const float cr0 = __expf(m0 - mn0), cr1 = __expf(m1 - mn1);
        float sum0 = 0.f, sum1 = 0.f;
        uint32_t pah[4][4];
#pragma unroll
        for (int kt = 0; kt < 4; kt++) {
#pragma unroll
            for (int hh = 0; hh < 2; hh++) {
                const int nt = 2 * kt + hh;
                float p00 = __expf(s[nt][0] - mn0);
                float p01 = __expf(s[nt][1] - mn0);
                float p10 = __expf(s[nt][2] - mn1);
                float p11 = __expf(s[nt][3] - mn1);
                sum0 += p00 + p01;
                sum1 += p10 + p11;
                pah[kt][hh * 2 + 0] = packh2(p00, p01);
                pah[kt][hh * 2 + 1] = packh2(p10, p11);
            }
        }
        sum0 += __shfl_xor_sync(0xffffffffu, sum0, 1);
        sum0 += __shfl_xor_sync(0xffffffffu, sum0, 2);
        sum1 += __shfl_xor_sync(0xffffffffu, sum1, 1);
        sum1 += __shfl_xor_sync(0xffffffffu, sum1, 2);
        l0 = l0 * cr0 + sum0;  m0 = mn0;
        l1 = l1 * cr1 + sum1;  m1 = mn1;
#pragma unroll
        for (int nt = 0; nt < 8; nt++) {
            o[nt][0] *= cr0; o[nt][1] *= cr0;
            o[nt][2] *= cr1; o[nt][3] *= cr1;
        }

        // ---- O += P V (1-pass), V via trans ldmatrix ----
#pragma unroll
        for (int kt = 0; kt < 4; kt++) {
#pragma unroll
            for (int p = 0; p < 4; p++) {
                uint32_t off = (uint32_t)(kt * 16 + vrow) * (APITCH * 2)
                             + (uint32_t)(p * 16 + vcol8) * 2;
                uint32_t fvh[4];
                ldm_x4_t(fvh, vh_b + off);
                mma16816(o[2*p],   pah[kt], fvh + 0);
                mma16816(o[2*p+1], pah[kt], fvh + 2);
            }
        }
        __syncthreads();
    }

    // ---- epilogue: normalize, store z hi ----
    const float inv0 = 1.f / l0, inv1 = 1.f / l1;
    const int gr0 = bb * SEQ + qb * 64 + wid * 16 + (lane >> 2);
    const int gc  = h * HDIM + (lane & 3) * 2;
#pragma unroll
    for (int nt = 0; nt < 8; nt++) {
        size_t off0 = (size_t)gr0 * MODEL + gc + nt * 8;
        size_t off1 = (size_t)(gr0 + 8) * MODEL + gc + nt * 8;
        *(uint32_t*)(zh + off0) = packh2(o[nt][0] * inv0, o[nt][1] * inv0);
        *(uint32_t*)(zh + off1) = packh2(o[nt][2] * inv1, o[nt][3] * inv1);
    }
}

// ---------------------------------------------------------------------------
// Launch
// ---------------------------------------------------------------------------
extern "C" void kernel_launch(void* const* d_in, const int* in_sizes, int n_in,
                              void* d_out, int out_size)
{
    const float* x      = (const float*)d_in[0];
    const float* W_attn = (const float*)d_in[1];
    const float* b_attn = (const float*)d_in[2];
    const float* W_proj = (const float*)d_in[3];
    const float* b_proj = (const float*)d_in[4];
    float* out = (float*)d_out;

    __half *qh, *ql, *xh, *xl, *wah, *wph, *zh;
    cudaGetSymbolAddress((void**)&qh,  g_qh);
    cudaGetSymbolAddress((void**)&ql,  g_ql);
    cudaGetSymbolAddress((void**)&xh,  g_xh);
    cudaGetSymbolAddress((void**)&xl,  g_xl);
    cudaGetSymbolAddress((void**)&wah, g_wah);
    cudaGetSymbolAddress((void**)&wph, g_wph);
    cudaGetSymbolAddress((void**)&zh,  g_zh);

    cudaFuncSetAttribute((const void*)gemm_mma<1,2>, cudaFuncAttributeMaxDynamicSharedMemorySize, GSMEM);
    cudaFuncSetAttribute((const void*)gemm_mma<0,1>, cudaFuncAttributeMaxDynamicSharedMemorySize, GSMEM);
    cudaFuncSetAttribute((const void*)attn_mma, cudaFuncAttributeMaxDynamicSharedMemorySize, ASMEMB);

    // Prep: split x (hi/lo); transpose weights (hi only)
    split_convert<<<(ROWS * KDIM / 4 + 255) / 256, 256>>>(x, xh, xl, ROWS * KDIM / 4);
    transpose_h<<<dim3(QKVN / 32, KDIM / 32), dim3(32, 8)>>>(W_attn, wah, KDIM, QKVN);
    transpose_h<<<dim3(MODEL / 32, KDIM / 32), dim3(32, 8)>>>(W_proj, wph, KDIM, MODEL);

    // QKV projection (2-pass) -> split fp16 qkv (q pre-scaled by 1/8)
    gemm_mma<1,2><<<dim3(QKVN / 128, ROWS / 128), 256, GSMEM>>>(
        xh, xl, wah, b_attn, nullptr, qh, ql, QKVN);

    // causal attention -> z (fp16 hi)
    attn_mma<<<dim3(SEQ / 64, HEADS, BATCH), 128, ASMEMB>>>(qh, ql, zh);

    // output projection (1-pass) -> fp32 out
    gemm_mma<0,1><<<dim3(MODEL / 128, ROWS / 128), 256, GSMEM>>>(
        zh, nullptr, wph, b_proj, out, nullptr, nullptr, MODEL);
}

// round 12
// speedup vs baseline: 2.3340x; 1.2291x over previous
#include <cuda_runtime.h>
#include <cuda_fp16.h>
#include <math_constants.h>
#include <cstdint>

// Problem constants
#define BATCH 2
#define SEQ   2048
#define MODEL 1024
#define HEADS 16
#define HDIM  64
#define ROWS  (BATCH*SEQ)          // 4096
#define QKVN  (3*MODEL)            // 3072
#define KDIM  1024

// ---------------------------------------------------------------------------
// Scratch (device globals: allocation-free)
// ---------------------------------------------------------------------------
__device__ __half g_qh[(size_t)ROWS * QKVN];   // qkv hi (q pre-scaled 1/8)
__device__ __half g_ql[(size_t)ROWS * QKVN];   // qkv lo (storage split; Q part read)
__device__ __half g_xh[(size_t)ROWS * KDIM];
__device__ __half g_wah[(size_t)QKVN * KDIM];  // W_attn^T hi only
__device__ __half g_wph[(size_t)MODEL * KDIM]; // W_proj^T hi only
__device__ __half g_zh[(size_t)ROWS * MODEL];  // z hi only

// ---------------------------------------------------------------------------
// Helpers
// ---------------------------------------------------------------------------
__device__ __forceinline__ uint32_t smem_u32(const void* p) {
    uint32_t a;
    asm("{ .reg .u64 t; cvta.to.shared.u64 t, %1; cvt.u32.u64 %0, t; }"
        : "=r"(a) : "l"(p));
    return a;
}
__device__ __forceinline__ void ldm_x4(uint32_t* r, uint32_t a) {
    asm volatile("ldmatrix.sync.aligned.m8n8.x4.shared.b16 {%0,%1,%2,%3}, [%4];"
        : "=r"(r[0]), "=r"(r[1]), "=r"(r[2]), "=r"(r[3]) : "r"(a));
}
__device__ __forceinline__ void ldm_x4_t(uint32_t* r, uint32_t a) {
    asm volatile("ldmatrix.sync.aligned.m8n8.x4.trans.shared.b16 {%0,%1,%2,%3}, [%4];"
        : "=r"(r[0]), "=r"(r[1]), "=r"(r[2]), "=r"(r[3]) : "r"(a));
}
__device__ __forceinline__ void mma16816(float* c, const uint32_t* a, const uint32_t* b) {
    asm volatile("mma.sync.aligned.m16n8k16.row.col.f32.f16.f16.f32 "
        "{%0,%1,%2,%3}, {%4,%5,%6,%7}, {%8,%9}, {%0,%1,%2,%3};"
        : "+f"(c[0]), "+f"(c[1]), "+f"(c[2]), "+f"(c[3])
        : "r"(a[0]), "r"(a[1]), "r"(a[2]), "r"(a[3]), "r"(b[0]), "r"(b[1]));
}
__device__ __forceinline__ void cp16(uint32_t saddr, const void* gaddr) {
    asm volatile("cp.async.cg.shared.global [%0], [%1], 16;" :: "r"(saddr), "l"(gaddr));
}
__device__ __forceinline__ uint32_t packh2(float lo, float hi) {
    __half2 p = __floats2half2_rn(lo, hi);
    return *reinterpret_cast<uint32_t*>(&p);
}

// ---------------------------------------------------------------------------
// Prep kernels
// ---------------------------------------------------------------------------
__global__ void convert_h(const float* __restrict__ x,
                          __half* __restrict__ h, int n4)
{
    int i = blockIdx.x * blockDim.x + threadIdx.x;
    if (i >= n4) return;
    float4 v = ((const float4*)x)[i];
    uint2 uh;
    uh.x = packh2(v.x, v.y);
    uh.y = packh2(v.z, v.w);
    ((uint2*)h)[i] = uh;
}

// W[K][N] fp32 -> W^T fp16 [N][K] (hi only)
__global__ void transpose_h(const float* __restrict__ W,
                            __half* __restrict__ Th, int Kd, int Nd)
{
    __shared__ float t[32][33];
    int n0 = blockIdx.x * 32, k0 = blockIdx.y * 32;
    int tx = threadIdx.x, ty = threadIdx.y;
#pragma unroll
    for (int j = 0; j < 32; j += 8)
        t[ty + j][tx] = W[(size_t)(k0 + ty + j) * Nd + n0 + tx];
    __syncthreads();
#pragma unroll
    for (int j = 0; j < 32; j += 8) {
        int n = n0 + ty + j, k = k0 + tx;
        Th[(size_t)n * Kd + k] = __float2half_rn(t[tx][ty + j]);
    }
}

// ---------------------------------------------------------------------------
// fp16 GEMM. PASSES=2: C = (Ah+Al) @ Bh^T;  PASSES=1: C = Ah @ Bh^T.  (+bias)
// BK=64, 3 tiles/stage layout, double-buffered, 2 CTAs/SM.
// MODE 0: C = fp32.  MODE 1: Ch/Cl = fp16 hi/lo of (acc+bias)*(col<MODEL?1/8:1)
// ---------------------------------------------------------------------------
#define GPITCH 144
#define GTILEB (128 * GPITCH)     // 18432
#define GSTAGEB (3 * GTILEB)      // 55296
#define GSMEM  (2 * GSTAGEB)      // 110592

template<int MODE, int PASSES>
__global__ __launch_bounds__(256, 2) void gemm_mma(
    const __half* __restrict__ Ah, const __half* __restrict__ Al,
    const __half* __restrict__ Bh,
    const float* __restrict__ bias, float* __restrict__ C,
    __half* __restrict__ Ch, __half* __restrict__ Cl, int Nd)
{
    extern __shared__ char smem[];
    const uint32_t sbase = smem_u32(smem);
    const int tid  = threadIdx.x;
    const int wid  = tid >> 5, lane = tid & 31;
    const int bn   = blockIdx.x * 128;
    const int bm   = blockIdx.y * 128;
    const int wm0  = (wid & 3) * 32;
    const int wn0  = (wid >> 2) * 64;

    const int lrow = tid >> 3;        // 0..31
    const int lc   = tid & 7;         // 16B chunk

    const __half* srcA_h = Ah + (size_t)(bm + lrow) * KDIM + lc * 8;
    const __half* srcA_l = (PASSES == 2) ? (Al + (size_t)(bm + lrow) * KDIM + lc * 8) : nullptr;
    const __half* srcB_h = Bh + (size_t)(bn + lrow) * KDIM + lc * 8;

    const int arow  = (lane & 7) + ((lane >> 3) & 1) * 8;
    const int acolB = ((lane >> 4) & 1) * 16;
    const int brow  = (lane & 7) + ((lane >> 4) & 1) * 8;
    const int bcolB = ((lane >> 3) & 1) * 16;

    float acc[16][4];
#pragma unroll
    for (int i = 0; i < 16; i++)
#pragma unroll
        for (int j = 0; j < 4; j++) acc[i][j] = 0.f;

    auto issue = [&](int stage, int k0) {
        uint32_t so = sbase + stage * GSTAGEB + lrow * GPITCH + lc * 16;
#pragma unroll
        for (int i = 0; i < 4; i++) {
            uint32_t sa = so + i * 32 * GPITCH;
            size_t   go = (size_t)i * 32 * KDIM + k0;
            cp16(sa,              srcA_h + go);
            if (PASSES == 2) cp16(sa + GTILEB, srcA_l + go);
            cp16(sa + 2 * GTILEB, srcB_h + go);
        }
        asm volatile("cp.async.commit_group;" ::: "memory");
    };

    issue(0, 0);

    for (int c = 0; c < 16; c++) {
        if (c + 1 < 16) {
            issue((c + 1) & 1, (c + 1) * 64);
            asm volatile("cp.async.wait_group 1;" ::: "memory");
        } else {
            asm volatile("cp.async.wait_group 0;" ::: "memory");
        }
        __syncthreads();

        const uint32_t ab  = sbase + (c & 1) * GSTAGEB;
        const uint32_t alb = ab + GTILEB;
        const uint32_t bb  = ab + 2 * GTILEB;

#pragma unroll
        for (int ks = 0; ks < 4; ks++) {
            uint32_t fah[2][4], fal[2][4], fbh[4][4];
#pragma unroll
            for (int ma = 0; ma < 2; ma++) {
                uint32_t off = (uint32_t)(wm0 + ma * 16 + arow) * GPITCH + ks * 32 + acolB;
                ldm_x4(fah[ma], ab + off);
                if (PASSES == 2) ldm_x4(fal[ma], alb + off);
            }
#pragma unroll
            for (int na = 0; na < 4; na++) {
                uint32_t off = (uint32_t)(wn0 + na * 16 + brow) * GPITCH + ks * 32 + bcolB;
                ldm_x4(fbh[na], bb + off);
            }
#pragma unroll
            for (int ma = 0; ma < 2; ma++) {
#pragma unroll
                for (int na = 0; na < 4; na++) {
                    float* c0 = acc[ma * 8 + na * 2];
                    float* c1 = acc[ma * 8 + na * 2 + 1];
                    mma16816(c0, fah[ma], fbh[na]);
                    mma16816(c1, fah[ma], fbh[na] + 2);
                    if (PASSES == 2) {
                        mma16816(c0, fal[ma], fbh[na]);
                        mma16816(c1, fal[ma], fbh[na] + 2);
                    }
                }
            }
        }
        __syncthreads();
    }

    const int er = bm + wm0 + (lane >> 2);
    const int ec = bn + wn0 + (lane & 3) * 2;
#pragma unroll
    for (int ma = 0; ma < 2; ma++) {
#pragma unroll
        for (int na = 0; na < 8; na++) {
            const float* a4 = acc[ma * 8 + na];
            int row = er + ma * 16;
            int col = ec + na * 8;
            float b0 = __ldg(bias + col), b1 = __ldg(bias + col + 1);
            if (MODE == 0) {
                float2 v0 = make_float2(a4[0] + b0, a4[1] + b1);
                float2 v1 = make_float2(a4[2] + b0, a4[3] + b1);
                *(float2*)(C + (size_t)row * Nd + col)       = v0;
                *(float2*)(C + (size_t)(row + 8) * Nd + col) = v1;
            } else {
                float sc = (col < MODEL) ? 0.125f : 1.f;
                float v0 = (a4[0] + b0) * sc, v1 = (a4[1] + b1) * sc;
                float v2 = (a4[2] + b0) * sc, v3 = (a4[3] + b1) * sc;
                __half h0 = __float2half_rn(v0), h1 = __float2half_rn(v1);
                __half h2 = __float2half_rn(v2), h3 = __float2half_rn(v3);
                size_t o0 = (size_t)row * Nd + col, o1 = (size_t)(row + 8) * Nd + col;
                *(uint32_t*)(Ch + o0) = packh2(v0, v1);
                *(uint32_t*)(Cl + o0) = packh2(v0 - __half2float(h0), v1 - __half2float(h1));
                *(uint32_t*)(Ch + o1) = packh2(v2, v3);
                *(uint32_t*)(Cl + o1) = packh2(v2 - __half2float(h2), v3 - __half2float(h3));
            }
        }
    }
}

// ---------------------------------------------------------------------------
// fp16 causal flash attention. QK^T: 2-pass (Q hi/lo, K hi). PV: 1-pass.
// CTA: 64 q-rows x (head, batch); heavy q-tiles scheduled FIRST (qb reversed).
// KV double-buffered via cp.async. Outputs z hi only.
// ---------------------------------------------------------------------------
#define APITCH 72                              // fp16/row (144 B)
#define ATILE  9216                            // 64*144
#define AQH 0
#define AQL ATILE
#define AKV0 (2 * ATILE)                       // stage: {Kh, Vh}
#define AKVSTAGE (2 * ATILE)                   // 18432
#define ASMEMB (2 * ATILE + 2 * AKVSTAGE)      // 55296

__global__ __launch_bounds__(128) void attn_mma(
    const __half* __restrict__ qh, const __half* __restrict__ ql,
    __half* __restrict__ zh)
{
    extern __shared__ __half asmem[];
    const uint32_t sb = smem_u32(asmem);
    const int tid = threadIdx.x, lane = tid & 31, wid = tid >> 5;
    const int qb = gridDim.x - 1 - blockIdx.x;   // heavy tiles first
    const int h = blockIdx.y, bb = blockIdx.z;

    const size_t rowbase = (size_t)(bb * SEQ) * QKVN;
    const int hc = h * HDIM;

    const int lr = tid >> 1;
    const int lc4 = (tid & 1) * 4;

    auto load_q = [&] {
#pragma unroll
        for (int j = 0; j < 4; j++) {
            size_t g = rowbase + (size_t)(qb * 64 + lr) * QKVN + hc + (lc4 + j) * 8;
            uint32_t d = (uint32_t)(lr * 144 + (lc4 + j) * 16);
            cp16(sb + AQH + d, qh + g);
            cp16(sb + AQL + d, ql + g);
        }
    };
    auto load_kv = [&](int stage, int kb) {
        uint32_t sbb = sb + AKV0 + stage * AKVSTAGE;
#pragma unroll
        for (int j = 0; j < 4; j++) {
            size_t gk = rowbase + (size_t)(kb * 64 + lr) * QKVN + MODEL + hc + (lc4 + j) * 8;
            uint32_t d = (uint32_t)(lr * 144 + (lc4 + j) * 16);
            cp16(sbb + d,         qh + gk);           // K hi
            cp16(sbb + ATILE + d, qh + gk + MODEL);   // V hi
        }
    };

    load_q();
    load_kv(0, 0);
    asm volatile("cp.async.commit_group;" ::: "memory");

    const int arow  = (lane & 7) + ((lane >> 3) & 1) * 8;
    const int acolB = ((lane >> 4) & 1) * 16;
    const int brow  = (lane & 7) + ((lane >> 4) & 1) * 8;
    const int bcolB = ((lane >> 3) & 1) * 16;
    const int vrow  = (lane & 7) + ((lane >> 3) & 1) * 8;
    const int vcol8 = ((lane >> 4) & 1) * 8;

    uint32_t qfh[4][4], qfl[4][4];
    float m0 = -CUDART_INF_F, m1 = -CUDART_INF_F, l0 = 0.f, l1 = 0.f;
    float o[8][4];
#pragma unroll
    for (int i = 0; i < 8; i++)
#pragma unroll
        for (int j = 0; j < 4; j++) o[i][j] = 0.f;

    for (int kb = 0; kb <= qb; kb++) {
        if (kb + 1 <= qb) {
            load_kv((kb + 1) & 1, kb + 1);
            asm volatile("cp.async.commit_group;" ::: "memory");
            asm volatile("cp.async.wait_group 1;" ::: "memory");
        } else {
            asm volatile("cp.async.wait_group 0;" ::: "memory");
        }
        __syncthreads();

        if (kb == 0) {
#pragma unroll
            for (int ks = 0; ks < 4; ks++) {
                uint32_t off = (uint32_t)(wid * 16 + arow) * (APITCH * 2) + ks * 32 + acolB;
                ldm_x4(qfh[ks], sb + AQH + off);
                ldm_x4(qfl[ks], sb + AQL + off);
            }
        }

        const uint32_t kvb = sb + AKV0 + (kb & 1) * AKVSTAGE;
        const uint32_t kh_b = kvb;
        const uint32_t vh_b = kvb + ATILE;

        // ---- S = Q K^T (2-pass) ----
        float s[8][4];
#pragma unroll
        for (int i = 0; i < 8; i++)
#pragma unroll
            for (int j = 0; j < 4; j++) s[i][j] = 0.f;
#pragma unroll
        for (int ks = 0; ks < 4; ks++) {
#pragma unroll
            for (int np = 0; np < 4; np++) {
                uint32_t off = (uint32_t)(np * 16 + brow) * (APITCH * 2) + ks * 32 + bcolB;
                uint32_t kh4[4];
                ldm_x4(kh4, kh_b + off);
                mma16816(s[2*np],   qfh[ks], kh4 + 0);
                mma16816(s[2*np+1], qfh[ks], kh4 + 2);
                mma16816(s[2*np],   qfl[ks], kh4 + 0);
                mma16816(s[2*np+1], qfl[ks], kh4 + 2);
            }
        }

        if (kb == qb) {
            const int rr0 = wid * 16 + (lane >> 2);
            const int cc0 = (lane & 3) * 2;
#pragma unroll
            for (int nt = 0; nt < 8; nt++) {
#pragma unroll
                for (int jj = 0; jj < 2; jj++) {
                    int col = nt * 8 + cc0 + jj;
                    if (col > rr0)     s[nt][jj]     = -CUDART_INF_F;
                    if (col > rr0 + 8) s[nt][2 + jj] = -CUDART_INF_F;
                }
            }
        }

        // ---- online softmax ----
        float mx0 = -CUDART_INF_F, mx1 = -CUDART_INF_F;
#pragma unroll
        for (int nt = 0; nt < 8; nt++) {
            mx0 = fmaxf(mx0, fmaxf(s[nt][0], s[nt][1]));
            mx1 = fmaxf(mx1, fmaxf(s[nt][2], s[nt][3]));
        }
        mx0 = fmaxf(mx0, __shfl_xor_sync(0xffffffffu, mx0, 1));
        mx0 = fmaxf(mx0, __shfl_xor_sync(0xffffffffu, mx0, 2));
        mx1 = fmaxf(mx1, __shfl_xor_sync(0xffffffffu, mx1, 1));
        mx1 = fmaxf(mx1, __shfl_xor_sync(0xffffffffu, mx1, 2));
        const float mn0 = fmaxf(m0, mx0), mn1 = fmaxf(m1, mx1);
        const float cr0 = __expf(m0 - mn0), cr1 = __expf(m1 - mn1);
        float sum0 = 0.f, sum1 = 0.f;
        uint32_t pah[4][4];
#pragma unroll
        for (int kt = 0; kt < 4; kt++) {
#pragma unroll
            for (int hh = 0; hh < 2; hh++) {
                const int nt = 2 * kt + hh;
                float p00 = __expf(s[nt][0] - mn0);
                float p01 = __expf(s[nt][1] - mn0);
                float p10 = __expf(s[nt][2] - mn1);
                float p11 = __expf(s[nt][3] - mn1);
                sum0 += p00 + p01;
                sum1 += p10 + p11;
                pah[kt][hh * 2 + 0] = packh2(p00, p01);
                pah[kt][hh * 2 + 1] = packh2(p10, p11);
            }
        }
        sum0 += __shfl_xor_sync(0xffffffffu, sum0, 1);
        sum0 += __shfl_xor_sync(0xffffffffu, sum0, 2);
        sum1 += __shfl_xor_sync(0xffffffffu, sum1, 1);
        sum1 += __shfl_xor_sync(0xffffffffu, sum1, 2);
        l0 = l0 * cr0 + sum0;  m0 = mn0;
        l1 = l1 * cr1 + sum1;  m1 = mn1;
#pragma unroll
        for (int nt = 0; nt < 8; nt++) {
            o[nt][0] *= cr0; o[nt][1] *= cr0;
            o[nt][2] *= cr1; o[nt][3] *= cr1;
        }

        // ---- O += P V (1-pass), V via trans ldmatrix ----
#pragma unroll
        for (int kt = 0; kt < 4; kt++) {
#pragma unroll
            for (int p = 0; p < 4; p++) {
                uint32_t off = (uint32_t)(kt * 16 + vrow) * (APITCH * 2)
                             + (uint32_t)(p * 16 + vcol8) * 2;
                uint32_t fvh[4];
                ldm_x4_t(fvh, vh_b + off);
                mma16816(o[2*p],   pah[kt], fvh + 0);
                mma16816(o[2*p+1], pah[kt], fvh + 2);
            }
        }
        __syncthreads();
    }

    // ---- epilogue: normalize, store z hi ----
    const float inv0 = 1.f / l0, inv1 = 1.f / l1;
    const int gr0 = bb * SEQ + qb * 64 + wid * 16 + (lane >> 2);
    const int gc  = h * HDIM + (lane & 3) * 2;
#pragma unroll
    for (int nt = 0; nt < 8; nt++) {
        size_t off0 = (size_t)gr0 * MODEL + gc + nt * 8;
        size_t off1 = (size_t)(gr0 + 8) * MODEL + gc + nt * 8;
        *(uint32_t*)(zh + off0) = packh2(o[nt][0] * inv0, o[nt][1] * inv0);
        *(uint32_t*)(zh + off1) = packh2(o[nt][2] * inv1, o[nt][3] * inv1);
    }
}

// ---------------------------------------------------------------------------
// Launch
// ---------------------------------------------------------------------------
extern "C" void kernel_launch(void* const* d_in, const int* in_sizes, int n_in,
                              void* d_out, int out_size)
{
    const float* x      = (const float*)d_in[0];
    const float* W_attn = (const float*)d_in[1];
    const float* b_attn = (const float*)d_in[2];
    const float* W_proj = (const float*)d_in[3];
    const float* b_proj = (const float*)d_in[4];
    float* out = (float*)d_out;

    __half *qh, *ql, *xh, *wah, *wph, *zh;
    cudaGetSymbolAddress((void**)&qh,  g_qh);
    cudaGetSymbolAddress((void**)&ql,  g_ql);
    cudaGetSymbolAddress((void**)&xh,  g_xh);
    cudaGetSymbolAddress((void**)&wah, g_wah);
    cudaGetSymbolAddress((void**)&wph, g_wph);
    cudaGetSymbolAddress((void**)&zh,  g_zh);

    cudaFuncSetAttribute((const void*)gemm_mma<1,1>, cudaFuncAttributeMaxDynamicSharedMemorySize, GSMEM);
    cudaFuncSetAttribute((const void*)gemm_mma<0,1>, cudaFuncAttributeMaxDynamicSharedMemorySize, GSMEM);
    cudaFuncSetAttribute((const void*)attn_mma, cudaFuncAttributeMaxDynamicSharedMemorySize, ASMEMB);

    // Prep: convert x to fp16 hi; transpose weights (hi only)
    convert_h<<<(ROWS * KDIM / 4 + 255) / 256, 256>>>(x, xh, ROWS * KDIM / 4);
    transpose_h<<<dim3(QKVN / 32, KDIM / 32), dim3(32, 8)>>>(W_attn, wah, KDIM, QKVN);
    transpose_h<<<dim3(MODEL / 32, KDIM / 32), dim3(32, 8)>>>(W_proj, wph, KDIM, MODEL);

    // QKV projection (1-pass) -> split fp16 qkv (q pre-scaled by 1/8)
    gemm_mma<1,1><<<dim3(QKVN / 128, ROWS / 128), 256, GSMEM>>>(
        xh, nullptr, wah, b_attn, nullptr, qh, ql, QKVN);

    // causal attention -> z (fp16 hi)
    attn_mma<<<dim3(SEQ / 64, HEADS, BATCH), 128, ASMEMB>>>(qh, ql, zh);

    // output projection (1-pass) -> fp32 out
    gemm_mma<0,1><<<dim3(MODEL / 128, ROWS / 128), 256, GSMEM>>>(
        zh, nullptr, wph, b_proj, out, nullptr, nullptr, MODEL);
}

// round 13
// speedup vs baseline: 2.5295x; 1.0838x over previous
#include <cuda_runtime.h>
#include <cuda_fp16.h>
#include <math_constants.h>
#include <cstdint>

// Problem constants
#define BATCH 2
#define SEQ   2048
#define MODEL 1024
#define HEADS 16
#define HDIM  64
#define ROWS  (BATCH*SEQ)          // 4096
#define QKVN  (3*MODEL)            // 3072
#define KDIM  1024

// ---------------------------------------------------------------------------
// Scratch (device globals: allocation-free)
// ---------------------------------------------------------------------------
__device__ __half g_qh[(size_t)ROWS * QKVN];   // qkv hi (q pre-scaled 1/8)
__device__ __half g_ql[(size_t)ROWS * QKVN];   // qkv lo (only q third written/read)
__device__ __half g_xh[(size_t)ROWS * KDIM];
__device__ __half g_wah[(size_t)QKVN * KDIM];  // W_attn^T hi only
__device__ __half g_wph[(size_t)MODEL * KDIM]; // W_proj^T hi only
__device__ __half g_zh[(size_t)ROWS * MODEL];  // z hi only

// ---------------------------------------------------------------------------
// Helpers
// ---------------------------------------------------------------------------
__device__ __forceinline__ uint32_t smem_u32(const void* p) {
    uint32_t a;
    asm("{ .reg .u64 t; cvta.to.shared.u64 t, %1; cvt.u32.u64 %0, t; }"
        : "=r"(a) : "l"(p));
    return a;
}
__device__ __forceinline__ void ldm_x4(uint32_t* r, uint32_t a) {
    asm volatile("ldmatrix.sync.aligned.m8n8.x4.shared.b16 {%0,%1,%2,%3}, [%4];"
        : "=r"(r[0]), "=r"(r[1]), "=r"(r[2]), "=r"(r[3]) : "r"(a));
}
__device__ __forceinline__ void ldm_x4_t(uint32_t* r, uint32_t a) {
    asm volatile("ldmatrix.sync.aligned.m8n8.x4.trans.shared.b16 {%0,%1,%2,%3}, [%4];"
        : "=r"(r[0]), "=r"(r[1]), "=r"(r[2]), "=r"(r[3]) : "r"(a));
}
__device__ __forceinline__ void mma16816(float* c, const uint32_t* a, const uint32_t* b) {
    asm volatile("mma.sync.aligned.m16n8k16.row.col.f32.f16.f16.f32 "
        "{%0,%1,%2,%3}, {%4,%5,%6,%7}, {%8,%9}, {%0,%1,%2,%3};"
        : "+f"(c[0]), "+f"(c[1]), "+f"(c[2]), "+f"(c[3])
        : "r"(a[0]), "r"(a[1]), "r"(a[2]), "r"(a[3]), "r"(b[0]), "r"(b[1]));
}
__device__ __forceinline__ void cp16(uint32_t saddr, const void* gaddr) {
    asm volatile("cp.async.cg.shared.global [%0], [%1], 16;" :: "r"(saddr), "l"(gaddr));
}
__device__ __forceinline__ uint32_t packh2(float lo, float hi) {
    __half2 p = __floats2half2_rn(lo, hi);
    return *reinterpret_cast<uint32_t*>(&p);
}

// ---------------------------------------------------------------------------
// Prep kernels
// ---------------------------------------------------------------------------
__global__ void convert_h(const float* __restrict__ x,
                          __half* __restrict__ h, int n4)
{
    int i = blockIdx.x * blockDim.x + threadIdx.x;
    if (i >= n4) return;
    float4 v = ((const float4*)x)[i];
    uint2 uh;
    uh.x = packh2(v.x, v.y);
    uh.y = packh2(v.z, v.w);
    ((uint2*)h)[i] = uh;
}

// W[K][N] fp32 -> W^T fp16 [N][K] (hi only)
__global__ void transpose_h(const float* __restrict__ W,
                            __half* __restrict__ Th, int Kd, int Nd)
{
    __shared__ float t[32][33];
    int n0 = blockIdx.x * 32, k0 = blockIdx.y * 32;
    int tx = threadIdx.x, ty = threadIdx.y;
#pragma unroll
    for (int j = 0; j < 32; j += 8)
        t[ty + j][tx] = W[(size_t)(k0 + ty + j) * Nd + n0 + tx];
    __syncthreads();
#pragma unroll
    for (int j = 0; j < 32; j += 8) {
        int n = n0 + ty + j, k = k0 + tx;
        Th[(size_t)n * Kd + k] = __float2half_rn(t[tx][ty + j]);
    }
}

// ---------------------------------------------------------------------------
// fp16 GEMM (1-pass): C = Ah @ Bh^T + bias.
// BK=64, double-buffered, 2 CTAs/SM.
// MODE 0: C = fp32.  MODE 1: Ch/Cl = fp16 hi/lo of (acc+bias)*(col<MODEL?1/8:1),
//         lo written only when bn < MODEL (only q third consumed downstream).
// ---------------------------------------------------------------------------
#define GPITCH 144
#define GTILEB (128 * GPITCH)     // 18432
#define GSTAGEB (3 * GTILEB)      // 55296 (A,(unused),B layout kept for simplicity)
#define GSMEM  (2 * GSTAGEB)      // 110592

template<int MODE>
__global__ __launch_bounds__(256, 2) void gemm_mma(
    const __half* __restrict__ Ah,
    const __half* __restrict__ Bh,
    const float* __restrict__ bias, float* __restrict__ C,
    __half* __restrict__ Ch, __half* __restrict__ Cl, int Nd)
{
    extern __shared__ char smem[];
    const uint32_t sbase = smem_u32(smem);
    const int tid  = threadIdx.x;
    const int wid  = tid >> 5, lane = tid & 31;
    const int bn   = blockIdx.x * 128;
    const int bm   = blockIdx.y * 128;
    const int wm0  = (wid & 3) * 32;
    const int wn0  = (wid >> 2) * 64;

    const int lrow = tid >> 3;        // 0..31
    const int lc   = tid & 7;         // 16B chunk

    const __half* srcA_h = Ah + (size_t)(bm + lrow) * KDIM + lc * 8;
    const __half* srcB_h = Bh + (size_t)(bn + lrow) * KDIM + lc * 8;

    const int arow  = (lane & 7) + ((lane >> 3) & 1) * 8;
    const int acolB = ((lane >> 4) & 1) * 16;
    const int brow  = (lane & 7) + ((lane >> 4) & 1) * 8;
    const int bcolB = ((lane >> 3) & 1) * 16;

    float acc[16][4];
#pragma unroll
    for (int i = 0; i < 16; i++)
#pragma unroll
        for (int j = 0; j < 4; j++) acc[i][j] = 0.f;

    auto issue = [&](int stage, int k0) {
        uint32_t so = sbase + stage * GSTAGEB + lrow * GPITCH + lc * 16;
#pragma unroll
        for (int i = 0; i < 4; i++) {
            uint32_t sa = so + i * 32 * GPITCH;
            size_t   go = (size_t)i * 32 * KDIM + k0;
            cp16(sa,              srcA_h + go);
            cp16(sa + 2 * GTILEB, srcB_h + go);
        }
        asm volatile("cp.async.commit_group;" ::: "memory");
    };

    issue(0, 0);

    for (int c = 0; c < 16; c++) {
        if (c + 1 < 16) {
            issue((c + 1) & 1, (c + 1) * 64);
            asm volatile("cp.async.wait_group 1;" ::: "memory");
        } else {
            asm volatile("cp.async.wait_group 0;" ::: "memory");
        }
        __syncthreads();

        const uint32_t ab  = sbase + (c & 1) * GSTAGEB;
        const uint32_t bb  = ab + 2 * GTILEB;

#pragma unroll
        for (int ks = 0; ks < 4; ks++) {
            uint32_t fah[2][4], fbh[4][4];
#pragma unroll
            for (int ma = 0; ma < 2; ma++) {
                uint32_t off = (uint32_t)(wm0 + ma * 16 + arow) * GPITCH + ks * 32 + acolB;
                ldm_x4(fah[ma], ab + off);
            }
#pragma unroll
            for (int na = 0; na < 4; na++) {
                uint32_t off = (uint32_t)(wn0 + na * 16 + brow) * GPITCH + ks * 32 + bcolB;
                ldm_x4(fbh[na], bb + off);
            }
#pragma unroll
            for (int ma = 0; ma < 2; ma++) {
#pragma unroll
                for (int na = 0; na < 4; na++) {
                    float* c0 = acc[ma * 8 + na * 2];
                    float* c1 = acc[ma * 8 + na * 2 + 1];
                    mma16816(c0, fah[ma], fbh[na]);
                    mma16816(c1, fah[ma], fbh[na] + 2);
                }
            }
        }
        __syncthreads();
    }

    const int er = bm + wm0 + (lane >> 2);
    const int ec = bn + wn0 + (lane & 3) * 2;
    const bool writeLo = (bn < MODEL);   // lo only consumed for q columns
#pragma unroll
    for (int ma = 0; ma < 2; ma++) {
#pragma unroll
        for (int na = 0; na < 8; na++) {
            const float* a4 = acc[ma * 8 + na];
            int row = er + ma * 16;
            int col = ec + na * 8;
            float b0 = __ldg(bias + col), b1 = __ldg(bias + col + 1);
            if (MODE == 0) {
                float2 v0 = make_float2(a4[0] + b0, a4[1] + b1);
                float2 v1 = make_float2(a4[2] + b0, a4[3] + b1);
                *(float2*)(C + (size_t)row * Nd + col)       = v0;
                *(float2*)(C + (size_t)(row + 8) * Nd + col) = v1;
            } else {
                float sc = (col < MODEL) ? 0.125f : 1.f;
                float v0 = (a4[0] + b0) * sc, v1 = (a4[1] + b1) * sc;
                float v2 = (a4[2] + b0) * sc, v3 = (a4[3] + b1) * sc;
                size_t o0 = (size_t)row * Nd + col, o1 = (size_t)(row + 8) * Nd + col;
                *(uint32_t*)(Ch + o0) = packh2(v0, v1);
                *(uint32_t*)(Ch + o1) = packh2(v2, v3);
                if (writeLo) {
                    __half h0 = __float2half_rn(v0), h1 = __float2half_rn(v1);
                    __half h2 = __float2half_rn(v2), h3 = __float2half_rn(v3);
                    *(uint32_t*)(Cl + o0) = packh2(v0 - __half2float(h0), v1 - __half2float(h1));
                    *(uint32_t*)(Cl + o1) = packh2(v2 - __half2float(h2), v3 - __half2float(h3));
                }
            }
        }
    }
}

// ---------------------------------------------------------------------------
// fp16 causal flash attention. 128 q-rows/CTA, 256 threads (8 warps x m16).
// QK^T: 2-pass (Q hi/lo, K hi). PV: 1-pass. KV tiles 64-wide, double-buffered.
// Warps fully above the diagonal skip the tile body. z hi only.
// ---------------------------------------------------------------------------
#define APITCH 72                              // fp16/row (144 B)
#define AQTILE (128 * 144)                     // 18432 (128 rows)
#define AKTILE (64 * 144)                      // 9216  (64 rows)
#define AQH 0
#define AQL AQTILE
#define AKV0 (2 * AQTILE)                      // stage: {Kh, Vh}
#define AKVSTAGE (2 * AKTILE)                  // 18432
#define ASMEMB (2 * AQTILE + 2 * AKVSTAGE)     // 73728

__global__ __launch_bounds__(256) void attn_mma(
    const __half* __restrict__ qh, const __half* __restrict__ ql,
    __half* __restrict__ zh)
{
    extern __shared__ __half asmem[];
    const uint32_t sb = smem_u32(asmem);
    const int tid = threadIdx.x, lane = tid & 31, wid = tid >> 5;
    const int qb = gridDim.x - 1 - blockIdx.x;   // heavy tiles first
    const int h = blockIdx.y, bb = blockIdx.z;

    const size_t rowbase = (size_t)(bb * SEQ) * QKVN;
    const int hc = h * HDIM;

    auto load_q = [&] {
#pragma unroll
        for (int j = 0; j < 4; j++) {
            int c = j * 256 + tid;             // 1024 chunks
            int r = c >> 3, ch = c & 7;
            size_t g = rowbase + (size_t)(qb * 128 + r) * QKVN + hc + ch * 8;
            uint32_t d = (uint32_t)(r * 144 + ch * 16);
            cp16(sb + AQH + d, qh + g);
            cp16(sb + AQL + d, ql + g);
        }
    };
    auto load_kv = [&](int stage, int kb) {
        uint32_t sbb = sb + AKV0 + stage * AKVSTAGE;
#pragma unroll
        for (int j = 0; j < 2; j++) {
            int c = j * 256 + tid;             // 512 chunks
            int r = c >> 3, ch = c & 7;
            size_t gk = rowbase + (size_t)(kb * 64 + r) * QKVN + MODEL + hc + ch * 8;
            uint32_t d = (uint32_t)(r * 144 + ch * 16);
            cp16(sbb + d,          qh + gk);           // K hi
            cp16(sbb + AKTILE + d, qh + gk + MODEL);   // V hi
        }
    };

    load_q();
    load_kv(0, 0);
    asm volatile("cp.async.commit_group;" ::: "memory");

    const int arow  = (lane & 7) + ((lane >> 3) & 1) * 8;
    const int acolB = ((lane >> 4) & 1) * 16;
    const int brow  = (lane & 7) + ((lane >> 4) & 1) * 8;
    const int bcolB = ((lane >> 3) & 1) * 16;
    const int vrow  = (lane & 7) + ((lane >> 3) & 1) * 8;
    const int vcol8 = ((lane >> 4) & 1) * 8;

    const int wr0 = qb * 128 + wid * 16;       // warp's global row base

    uint32_t qfh[4][4], qfl[4][4];
    float m0 = -CUDART_INF_F, m1 = -CUDART_INF_F, l0 = 0.f, l1 = 0.f;
    float o[8][4];
#pragma unroll
    for (int i = 0; i < 8; i++)
#pragma unroll
        for (int j = 0; j < 4; j++) o[i][j] = 0.f;

    const int kbmax = 2 * qb + 1;
    for (int kb = 0; kb <= kbmax; kb++) {
        if (kb + 1 <= kbmax) {
            load_kv((kb + 1) & 1, kb + 1);
            asm volatile("cp.async.commit_group;" ::: "memory");
            asm volatile("cp.async.wait_group 1;" ::: "memory");
        } else {
            asm volatile("cp.async.wait_group 0;" ::: "memory");
        }
        __syncthreads();

        if (kb == 0) {
#pragma unroll
            for (int ks = 0; ks < 4; ks++) {
                uint32_t off = (uint32_t)(wid * 16 + arow) * (APITCH * 2) + ks * 32 + acolB;
                ldm_x4(qfh[ks], sb + AQH + off);
                ldm_x4(qfl[ks], sb + AQL + off);
            }
        }

        // warp fully above diagonal for this kv tile -> skip body (syncs uniform)
        if (kb * 64 <= wr0 + 15) {
            const uint32_t kvb = sb + AKV0 + (kb & 1) * AKVSTAGE;
            const uint32_t kh_b = kvb;
            const uint32_t vh_b = kvb + AKTILE;

            // ---- S = Q K^T (2-pass) ----
            float s[8][4];
#pragma unroll
            for (int i = 0; i < 8; i++)
#pragma unroll
                for (int j = 0; j < 4; j++) s[i][j] = 0.f;
#pragma unroll
            for (int ks = 0; ks < 4; ks++) {
#pragma unroll
                for (int np = 0; np < 4; np++) {
                    uint32_t off = (uint32_t)(np * 16 + brow) * (APITCH * 2) + ks * 32 + bcolB;
                    uint32_t kh4[4];
                    ldm_x4(kh4, kh_b + off);
                    mma16816(s[2*np],   qfh[ks], kh4 + 0);
                    mma16816(s[2*np+1], qfh[ks], kh4 + 2);
                    mma16816(s[2*np],   qfl[ks], kh4 + 0);
                    mma16816(s[2*np+1], qfl[ks], kh4 + 2);
                }
            }

            // ---- causal mask when kv tile overlaps the diagonal ----
            if (kb * 64 + 63 > wr0) {
                const int rr0 = wr0 + (lane >> 2);
                const int cc0 = kb * 64 + (lane & 3) * 2;
#pragma unroll
                for (int nt = 0; nt < 8; nt++) {
#pragma unroll
                    for (int jj = 0; jj < 2; jj++) {
                        int col = cc0 + nt * 8 + jj;
                        if (col > rr0)     s[nt][jj]     = -CUDART_INF_F;
                        if (col > rr0 + 8) s[nt][2 + jj] = -CUDART_INF_F;
                    }
                }
            }

            // ---- online softmax ----
            float mx0 = -CUDART_INF_F, mx1 = -CUDART_INF_F;
#pragma unroll
            for (int nt = 0; nt < 8; nt++) {
                mx0 = fmaxf(mx0, fmaxf(s[nt][0], s[nt][1]));
                mx1 = fmaxf(mx1, fmaxf(s[nt][2], s[nt][3]));
            }
            mx0 = fmaxf(mx0, __shfl_xor_sync(0xffffffffu, mx0, 1));
            mx0 = fmaxf(mx0, __shfl_xor_sync(0xffffffffu, mx0, 2));
            mx1 = fmaxf(mx1, __shfl_xor_sync(0xffffffffu, mx1, 1));
            mx1 = fmaxf(mx1, __shfl_xor_sync(0xffffffffu, mx1, 2));
            const float mn0 = fmaxf(m0, mx0), mn1 = fmaxf(m1, mx1);
            const float cr0 = __expf(m0 - mn0), cr1 = __expf(m1 - mn1);
            float sum0 = 0.f, sum1 = 0.f;
            uint32_t pah[4][4];
#pragma unroll
            for (int kt = 0; kt < 4; kt++) {
#pragma unroll
                for (int hh = 0; hh < 2; hh++) {
                    const int nt = 2 * kt + hh;
                    float p00 = __expf(s[nt][0] - mn0);
                    float p01 = __expf(s[nt][1] - mn0);
                    float p10 = __expf(s[nt][2] - mn1);
                    float p11 = __expf(s[nt][3] - mn1);
                    sum0 += p00 + p01;
                    sum1 += p10 + p11;
                    pah[kt][hh * 2 + 0] = packh2(p00, p01);
                    pah[kt][hh * 2 + 1] = packh2(p10, p11);
                }
            }
            sum0 += __shfl_xor_sync(0xffffffffu, sum0, 1);
            sum0 += __shfl_xor_sync(0xffffffffu, sum0, 2);
            sum1 += __shfl_xor_sync(0xffffffffu, sum1, 1);
            sum1 += __shfl_xor_sync(0xffffffffu, sum1, 2);
            l0 = l0 * cr0 + sum0;  m0 = mn0;
            l1 = l1 * cr1 + sum1;  m1 = mn1;
#pragma unroll
            for (int nt = 0; nt < 8; nt++) {
                o[nt][0] *= cr0; o[nt][1] *= cr0;
                o[nt][2] *= cr1; o[nt][3] *= cr1;
            }

            // ---- O += P V (1-pass), V via trans ldmatrix ----
#pragma unroll
            for (int kt = 0; kt < 4; kt++) {
#pragma unroll
                for (int p = 0; p < 4; p++) {
                    uint32_t off = (uint32_t)(kt * 16 + vrow) * (APITCH * 2)
                                 + (uint32_t)(p * 16 + vcol8) * 2;
                    uint32_t fvh[4];
                    ldm_x4_t(fvh, vh_b + off);
                    mma16816(o[2*p],   pah[kt], fvh + 0);
                    mma16816(o[2*p+1], pah[kt], fvh + 2);
                }
            }
        }
        __syncthreads();
    }

    // ---- epilogue: normalize, store z hi ----
    const float inv0 = 1.f / l0, inv1 = 1.f / l1;
    const int gr0 = bb * SEQ + qb * 128 + wid * 16 + (lane >> 2);
    const int gc  = h * HDIM + (lane & 3) * 2;
#pragma unroll
    for (int nt = 0; nt < 8; nt++) {
        size_t off0 = (size_t)gr0 * MODEL + gc + nt * 8;
        size_t off1 = (size_t)(gr0 + 8) * MODEL + gc + nt * 8;
        *(uint32_t*)(zh + off0) = packh2(o[nt][0] * inv0, o[nt][1] * inv0);
        *(uint32_t*)(zh + off1) = packh2(o[nt][2] * inv1, o[nt][3] * inv1);
    }
}

// ---------------------------------------------------------------------------
// Launch
// ---------------------------------------------------------------------------
extern "C" void kernel_launch(void* const* d_in, const int* in_sizes, int n_in,
                              void* d_out, int out_size)
{
    const float* x      = (const float*)d_in[0];
    const float* W_attn = (const float*)d_in[1];
    const float* b_attn = (const float*)d_in[2];
    const float* W_proj = (const float*)d_in[3];
    const float* b_proj = (const float*)d_in[4];
    float* out = (float*)d_out;

    __half *qh, *ql, *xh, *wah, *wph, *zh;
    cudaGetSymbolAddress((void**)&qh,  g_qh);
    cudaGetSymbolAddress((void**)&ql,  g_ql);
    cudaGetSymbolAddress((void**)&xh,  g_xh);
    cudaGetSymbolAddress((void**)&wah, g_wah);
    cudaGetSymbolAddress((void**)&wph, g_wph);
    cudaGetSymbolAddress((void**)&zh,  g_zh);

    cudaFuncSetAttribute((const void*)gemm_mma<1>, cudaFuncAttributeMaxDynamicSharedMemorySize, GSMEM);
    cudaFuncSetAttribute((const void*)gemm_mma<0>, cudaFuncAttributeMaxDynamicSharedMemorySize, GSMEM);
    cudaFuncSetAttribute((const void*)attn_mma, cudaFuncAttributeMaxDynamicSharedMemorySize, ASMEMB);

    // Prep: convert x to fp16 hi; transpose weights (hi only)
    convert_h<<<(ROWS * KDIM / 4 + 255) / 256, 256>>>(x, xh, ROWS * KDIM / 4);
    transpose_h<<<dim3(QKVN / 32, KDIM / 32), dim3(32, 8)>>>(W_attn, wah, KDIM, QKVN);
    transpose_h<<<dim3(MODEL / 32, KDIM / 32), dim3(32, 8)>>>(W_proj, wph, KDIM, MODEL);

    // QKV projection (1-pass) -> split fp16 qkv (q pre-scaled by 1/8)
    gemm_mma<1><<<dim3(QKVN / 128, ROWS / 128), 256, GSMEM>>>(
        xh, wah, b_attn, nullptr, qh, ql, QKVN);

    // causal attention -> z (fp16 hi)
    attn_mma<<<dim3(SEQ / 128, HEADS, BATCH), 256, ASMEMB>>>(qh, ql, zh);

    // output projection (1-pass) -> fp32 out
    gemm_mma<0><<<dim3(MODEL / 128, ROWS / 128), 256, GSMEM>>>(
        zh, wph, b_proj, out, nullptr, nullptr, MODEL);
}

// round 14
// speedup vs baseline: 2.8046x; 1.1087x over previous
#include <cuda_runtime.h>
#include <cuda_fp16.h>
#include <math_constants.h>
#include <cstdint>

// Problem constants
#define BATCH 2
#define SEQ   2048
#define MODEL 1024
#define HEADS 16
#define HDIM  64
#define ROWS  (BATCH*SEQ)          // 4096
#define QKVN  (3*MODEL)            // 3072
#define KDIM  1024

// ---------------------------------------------------------------------------
// Scratch (device globals: allocation-free)
// ---------------------------------------------------------------------------
__device__ __half g_qh[(size_t)ROWS * QKVN];   // qkv hi (q pre-scaled 1/8)
__device__ __half g_xh[(size_t)ROWS * KDIM];
__device__ __half g_wah[(size_t)QKVN * KDIM];  // W_attn^T hi
__device__ __half g_wph[(size_t)MODEL * KDIM]; // W_proj^T hi
__device__ __half g_zh[(size_t)ROWS * MODEL];  // z hi

// ---------------------------------------------------------------------------
// Helpers
// ---------------------------------------------------------------------------
__device__ __forceinline__ uint32_t smem_u32(const void* p) {
    uint32_t a;
    asm("{ .reg .u64 t; cvta.to.shared.u64 t, %1; cvt.u32.u64 %0, t; }"
        : "=r"(a) : "l"(p));
    return a;
}
__device__ __forceinline__ void ldm_x4(uint32_t* r, uint32_t a) {
    asm volatile("ldmatrix.sync.aligned.m8n8.x4.shared.b16 {%0,%1,%2,%3}, [%4];"
        : "=r"(r[0]), "=r"(r[1]), "=r"(r[2]), "=r"(r[3]) : "r"(a));
}
__device__ __forceinline__ void ldm_x4_t(uint32_t* r, uint32_t a) {
    asm volatile("ldmatrix.sync.aligned.m8n8.x4.trans.shared.b16 {%0,%1,%2,%3}, [%4];"
        : "=r"(r[0]), "=r"(r[1]), "=r"(r[2]), "=r"(r[3]) : "r"(a));
}
__device__ __forceinline__ void mma16816(float* c, const uint32_t* a, const uint32_t* b) {
    asm volatile("mma.sync.aligned.m16n8k16.row.col.f32.f16.f16.f32 "
        "{%0,%1,%2,%3}, {%4,%5,%6,%7}, {%8,%9}, {%0,%1,%2,%3};"
        : "+f"(c[0]), "+f"(c[1]), "+f"(c[2]), "+f"(c[3])
        : "r"(a[0]), "r"(a[1]), "r"(a[2]), "r"(a[3]), "r"(b[0]), "r"(b[1]));
}
__device__ __forceinline__ void cp16(uint32_t saddr, const void* gaddr) {
    asm volatile("cp.async.cg.shared.global [%0], [%1], 16;" :: "r"(saddr), "l"(gaddr));
}
__device__ __forceinline__ uint32_t packh2(float lo, float hi) {
    __half2 p = __floats2half2_rn(lo, hi);
    return *reinterpret_cast<uint32_t*>(&p);
}

// ---------------------------------------------------------------------------
// Prep kernels
// ---------------------------------------------------------------------------
__global__ void convert_h(const float* __restrict__ x,
                          __half* __restrict__ h, int n4)
{
    int i = blockIdx.x * blockDim.x + threadIdx.x;
    if (i >= n4) return;
    float4 v = ((const float4*)x)[i];
    uint2 uh;
    uh.x = packh2(v.x, v.y);
    uh.y = packh2(v.z, v.w);
    ((uint2*)h)[i] = uh;
}

// W[K][N] fp32 -> W^T fp16 [N][K]
__global__ void transpose_h(const float* __restrict__ W,
                            __half* __restrict__ Th, int Kd, int Nd)
{
    __shared__ float t[32][33];
    int n0 = blockIdx.x * 32, k0 = blockIdx.y * 32;
    int tx = threadIdx.x, ty = threadIdx.y;
#pragma unroll
    for (int j = 0; j < 32; j += 8)
        t[ty + j][tx] = W[(size_t)(k0 + ty + j) * Nd + n0 + tx];
    __syncthreads();
#pragma unroll
    for (int j = 0; j < 32; j += 8) {
        int n = n0 + ty + j, k = k0 + tx;
        Th[(size_t)n * Kd + k] = __float2half_rn(t[tx][ty + j]);
    }
}

// ---------------------------------------------------------------------------
// fp16 GEMM (1-pass): C = Ah @ Bh^T + bias.  BK=64, double-buffered, 2 CTAs/SM.
// MODE 0: C = fp32.  MODE 1: Ch = fp16 of (acc+bias)*(col<MODEL ? 1/8 : 1)
// ---------------------------------------------------------------------------
#define GPITCH 144
#define GTILEB (128 * GPITCH)     // 18432
#define GSTAGEB (3 * GTILEB)      // 55296 (A, pad, B)
#define GSMEM  (2 * GSTAGEB)      // 110592

template<int MODE>
__global__ __launch_bounds__(256, 2) void gemm_mma(
    const __half* __restrict__ Ah,
    const __half* __restrict__ Bh,
    const float* __restrict__ bias, float* __restrict__ C,
    __half* __restrict__ Ch, int Nd)
{
    extern __shared__ char smem[];
    const uint32_t sbase = smem_u32(smem);
    const int tid  = threadIdx.x;
    const int wid  = tid >> 5, lane = tid & 31;
    const int bn   = blockIdx.x * 128;
    const int bm   = blockIdx.y * 128;
    const int wm0  = (wid & 3) * 32;
    const int wn0  = (wid >> 2) * 64;

    const int lrow = tid >> 3;
    const int lc   = tid & 7;

    const __half* srcA_h = Ah + (size_t)(bm + lrow) * KDIM + lc * 8;
    const __half* srcB_h = Bh + (size_t)(bn + lrow) * KDIM + lc * 8;

    const int arow  = (lane & 7) + ((lane >> 3) & 1) * 8;
    const int acolB = ((lane >> 4) & 1) * 16;
    const int brow  = (lane & 7) + ((lane >> 4) & 1) * 8;
    const int bcolB = ((lane >> 3) & 1) * 16;

    float acc[16][4];
#pragma unroll
    for (int i = 0; i < 16; i++)
#pragma unroll
        for (int j = 0; j < 4; j++) acc[i][j] = 0.f;

    auto issue = [&](int stage, int k0) {
        uint32_t so = sbase + stage * GSTAGEB + lrow * GPITCH + lc * 16;
#pragma unroll
        for (int i = 0; i < 4; i++) {
            uint32_t sa = so + i * 32 * GPITCH;
            size_t   go = (size_t)i * 32 * KDIM + k0;
            cp16(sa,              srcA_h + go);
            cp16(sa + 2 * GTILEB, srcB_h + go);
        }
        asm volatile("cp.async.commit_group;" ::: "memory");
    };

    issue(0, 0);

    for (int c = 0; c < 16; c++) {
        if (c + 1 < 16) {
            issue((c + 1) & 1, (c + 1) * 64);
            asm volatile("cp.async.wait_group 1;" ::: "memory");
        } else {
            asm volatile("cp.async.wait_group 0;" ::: "memory");
        }
        __syncthreads();

        const uint32_t ab  = sbase + (c & 1) * GSTAGEB;
        const uint32_t bb  = ab + 2 * GTILEB;

#pragma unroll
        for (int ks = 0; ks < 4; ks++) {
            uint32_t fah[2][4], fbh[4][4];
#pragma unroll
            for (int ma = 0; ma < 2; ma++) {
                uint32_t off = (uint32_t)(wm0 + ma * 16 + arow) * GPITCH + ks * 32 + acolB;
                ldm_x4(fah[ma], ab + off);
            }
#pragma unroll
            for (int na = 0; na < 4; na++) {
                uint32_t off = (uint32_t)(wn0 + na * 16 + brow) * GPITCH + ks * 32 + bcolB;
                ldm_x4(fbh[na], bb + off);
            }
#pragma unroll
            for (int ma = 0; ma < 2; ma++) {
#pragma unroll
                for (int na = 0; na < 4; na++) {
                    float* c0 = acc[ma * 8 + na * 2];
                    float* c1 = acc[ma * 8 + na * 2 + 1];
                    mma16816(c0, fah[ma], fbh[na]);
                    mma16816(c1, fah[ma], fbh[na] + 2);
                }
            }
        }
        __syncthreads();
    }

    const int er = bm + wm0 + (lane >> 2);
    const int ec = bn + wn0 + (lane & 3) * 2;
#pragma unroll
    for (int ma = 0; ma < 2; ma++) {
#pragma unroll
        for (int na = 0; na < 8; na++) {
            const float* a4 = acc[ma * 8 + na];
            int row = er + ma * 16;
            int col = ec + na * 8;
            float b0 = __ldg(bias + col), b1 = __ldg(bias + col + 1);
            if (MODE == 0) {
                float2 v0 = make_float2(a4[0] + b0, a4[1] + b1);
                float2 v1 = make_float2(a4[2] + b0, a4[3] + b1);
                *(float2*)(C + (size_t)row * Nd + col)       = v0;
                *(float2*)(C + (size_t)(row + 8) * Nd + col) = v1;
            } else {
                float sc = (col < MODEL) ? 0.125f : 1.f;
                size_t o0 = (size_t)row * Nd + col, o1 = (size_t)(row + 8) * Nd + col;
                *(uint32_t*)(Ch + o0) = packh2((a4[0] + b0) * sc, (a4[1] + b1) * sc);
                *(uint32_t*)(Ch + o1) = packh2((a4[2] + b0) * sc, (a4[3] + b1) * sc);
            }
        }
    }
}

// ---------------------------------------------------------------------------
// fp16 causal flash attention, all 1-pass. 128 q-rows/CTA, 256 threads.
// KV tiles 64-wide, double-buffered; 2 CTAs/SM. z hi only.
// ---------------------------------------------------------------------------
#define APITCH 72                              // fp16/row (144 B)
#define AQTILE (128 * 144)                     // 18432
#define AKTILE (64 * 144)                      // 9216
#define AQH 0
#define AKV0 AQTILE                            // stage: {Kh, Vh}
#define AKVSTAGE (2 * AKTILE)                  // 18432
#define ASMEMB (AQTILE + 2 * AKVSTAGE)         // 55296

__global__ __launch_bounds__(256, 2) void attn_mma(
    const __half* __restrict__ qh,
    __half* __restrict__ zh)
{
    extern __shared__ __half asmem[];
    const uint32_t sb = smem_u32(asmem);
    const int tid = threadIdx.x, lane = tid & 31, wid = tid >> 5;
    const int qb = gridDim.x - 1 - blockIdx.x;   // heavy tiles first
    const int h = blockIdx.y, bb = blockIdx.z;

    const size_t rowbase = (size_t)(bb * SEQ) * QKVN;
    const int hc = h * HDIM;

    auto load_q = [&] {
#pragma unroll
        for (int j = 0; j < 4; j++) {
            int c = j * 256 + tid;             // 1024 chunks
            int r = c >> 3, ch = c & 7;
            size_t g = rowbase + (size_t)(qb * 128 + r) * QKVN + hc + ch * 8;
            cp16(sb + AQH + (uint32_t)(r * 144 + ch * 16), qh + g);
        }
    };
    auto load_kv = [&](int stage, int kb) {
        uint32_t sbb = sb + AKV0 + stage * AKVSTAGE;
#pragma unroll
        for (int j = 0; j < 2; j++) {
            int c = j * 256 + tid;             // 512 chunks
            int r = c >> 3, ch = c & 7;
            size_t gk = rowbase + (size_t)(kb * 64 + r) * QKVN + MODEL + hc + ch * 8;
            uint32_t d = (uint32_t)(r * 144 + ch * 16);
            cp16(sbb + d,          qh + gk);           // K hi
            cp16(sbb + AKTILE + d, qh + gk + MODEL);   // V hi
        }
    };

    load_q();
    load_kv(0, 0);
    asm volatile("cp.async.commit_group;" ::: "memory");

    const int arow  = (lane & 7) + ((lane >> 3) & 1) * 8;
    const int acolB = ((lane >> 4) & 1) * 16;
    const int brow  = (lane & 7) + ((lane >> 4) & 1) * 8;
    const int bcolB = ((lane >> 3) & 1) * 16;
    const int vrow  = (lane & 7) + ((lane >> 3) & 1) * 8;
    const int vcol8 = ((lane >> 4) & 1) * 8;

    const int wr0 = qb * 128 + wid * 16;       // warp's global row base

    uint32_t qfh[4][4];
    float m0 = -CUDART_INF_F, m1 = -CUDART_INF_F, l0 = 0.f, l1 = 0.f;
    float o[8][4];
#pragma unroll
    for (int i = 0; i < 8; i++)
#pragma unroll
        for (int j = 0; j < 4; j++) o[i][j] = 0.f;

    const int kbmax = 2 * qb + 1;
    for (int kb = 0; kb <= kbmax; kb++) {
        if (kb + 1 <= kbmax) {
            load_kv((kb + 1) & 1, kb + 1);
            asm volatile("cp.async.commit_group;" ::: "memory");
            asm volatile("cp.async.wait_group 1;" ::: "memory");
        } else {
            asm volatile("cp.async.wait_group 0;" ::: "memory");
        }
        __syncthreads();

        if (kb == 0) {
#pragma unroll
            for (int ks = 0; ks < 4; ks++) {
                uint32_t off = (uint32_t)(wid * 16 + arow) * (APITCH * 2) + ks * 32 + acolB;
                ldm_x4(qfh[ks], sb + AQH + off);
            }
        }

        // warp fully above diagonal for this kv tile -> skip body (syncs uniform)
        if (kb * 64 <= wr0 + 15) {
            const uint32_t kvb = sb + AKV0 + (kb & 1) * AKVSTAGE;
            const uint32_t kh_b = kvb;
            const uint32_t vh_b = kvb + AKTILE;

            // ---- S = Q K^T (1-pass) ----
            float s[8][4];
#pragma unroll
            for (int i = 0; i < 8; i++)
#pragma unroll
                for (int j = 0; j < 4; j++) s[i][j] = 0.f;
#pragma unroll
            for (int ks = 0; ks < 4; ks++) {
#pragma unroll
                for (int np = 0; np < 4; np++) {
                    uint32_t off = (uint32_t)(np * 16 + brow) * (APITCH * 2) + ks * 32 + bcolB;
                    uint32_t kh4[4];
                    ldm_x4(kh4, kh_b + off);
                    mma16816(s[2*np],   qfh[ks], kh4 + 0);
                    mma16816(s[2*np+1], qfh[ks], kh4 + 2);
                }
            }

            // ---- causal mask when kv tile overlaps the diagonal ----
            if (kb * 64 + 63 > wr0) {
                const int rr0 = wr0 + (lane >> 2);
                const int cc0 = kb * 64 + (lane & 3) * 2;
#pragma unroll
                for (int nt = 0; nt < 8; nt++) {
#pragma unroll
                    for (int jj = 0; jj < 2; jj++) {
                        int col = cc0 + nt * 8 + jj;
                        if (col > rr0)     s[nt][jj]     = -CUDART_INF_F;
                        if (col > rr0 + 8) s[nt][2 + jj] = -CUDART_INF_F;
                    }
                }
            }

            // ---- online softmax ----
            float mx0 = -CUDART_INF_F, mx1 = -CUDART_INF_F;
#pragma unroll
            for (int nt = 0; nt < 8; nt++) {
                mx0 = fmaxf(mx0, fmaxf(s[nt][0], s[nt][1]));
                mx1 = fmaxf(mx1, fmaxf(s[nt][2], s[nt][3]));
            }
            mx0 = fmaxf(mx0, __shfl_xor_sync(0xffffffffu, mx0, 1));
            mx0 = fmaxf(mx0, __shfl_xor_sync(0xffffffffu, mx0, 2));
            mx1 = fmaxf(mx1, __shfl_xor_sync(0xffffffffu, mx1, 1));
            mx1 = fmaxf(mx1, __shfl_xor_sync(0xffffffffu, mx1, 2));
            const float mn0 = fmaxf(m0, mx0), mn1 = fmaxf(m1, mx1);
            const float cr0 = __expf(m0 - mn0), cr1 = __expf(m1 - mn1);
            float sum0 = 0.f, sum1 = 0.f;
            uint32_t pah[4][4];
#pragma unroll
            for (int kt = 0; kt < 4; kt++) {
#pragma unroll
                for (int hh = 0; hh < 2; hh++) {
                    const int nt = 2 * kt + hh;
                    float p00 = __expf(s[nt][0] - mn0);
                    float p01 = __expf(s[nt][1] - mn0);
                    float p10 = __expf(s[nt][2] - mn1);
                    float p11 = __expf(s[nt][3] - mn1);
                    sum0 += p00 + p01;
                    sum1 += p10 + p11;
                    pah[kt][hh * 2 + 0] = packh2(p00, p01);
                    pah[kt][hh * 2 + 1] = packh2(p10, p11);
                }
            }
            sum0 += __shfl_xor_sync(0xffffffffu, sum0, 1);
            sum0 += __shfl_xor_sync(0xffffffffu, sum0, 2);
            sum1 += __shfl_xor_sync(0xffffffffu, sum1, 1);
            sum1 += __shfl_xor_sync(0xffffffffu, sum1, 2);
            l0 = l0 * cr0 + sum0;  m0 = mn0;
            l1 = l1 * cr1 + sum1;  m1 = mn1;
#pragma unroll
            for (int nt = 0; nt < 8; nt++) {
                o[nt][0] *= cr0; o[nt][1] *= cr0;
                o[nt][2] *= cr1; o[nt][3] *= cr1;
            }

            // ---- O += P V (1-pass), V via trans ldmatrix ----
#pragma unroll
            for (int kt = 0; kt < 4; kt++) {
#pragma unroll
                for (int p = 0; p < 4; p++) {
                    uint32_t off = (uint32_t)(kt * 16 + vrow) * (APITCH * 2)
                                 + (uint32_t)(p * 16 + vcol8) * 2;
                    uint32_t fvh[4];
                    ldm_x4_t(fvh, vh_b + off);
                    mma16816(o[2*p],   pah[kt], fvh + 0);
                    mma16816(o[2*p+1], pah[kt], fvh + 2);
                }
            }
        }
        __syncthreads();
    }

    // ---- epilogue: normalize, store z hi ----
    const float inv0 = 1.f / l0, inv1 = 1.f / l1;
    const int gr0 = bb * SEQ + qb * 128 + wid * 16 + (lane >> 2);
    const int gc  = h * HDIM + (lane & 3) * 2;
#pragma unroll
    for (int nt = 0; nt < 8; nt++) {
        size_t off0 = (size_t)gr0 * MODEL + gc + nt * 8;
        size_t off1 = (size_t)(gr0 + 8) * MODEL + gc + nt * 8;
        *(uint32_t*)(zh + off0) = packh2(o[nt][0] * inv0, o[nt][1] * inv0);
        *(uint32_t*)(zh + off1) = packh2(o[nt][2] * inv1, o[nt][3] * inv1);
    }
}

// ---------------------------------------------------------------------------
// Launch
// ---------------------------------------------------------------------------
extern "C" void kernel_launch(void* const* d_in, const int* in_sizes, int n_in,
                              void* d_out, int out_size)
{
    const float* x      = (const float*)d_in[0];
    const float* W_attn = (const float*)d_in[1];
    const float* b_attn = (const float*)d_in[2];
    const float* W_proj = (const float*)d_in[3];
    const float* b_proj = (const float*)d_in[4];
    float* out = (float*)d_out;

    __half *qh, *xh, *wah, *wph, *zh;
    cudaGetSymbolAddress((void**)&qh,  g_qh);
    cudaGetSymbolAddress((void**)&xh,  g_xh);
    cudaGetSymbolAddress((void**)&wah, g_wah);
    cudaGetSymbolAddress((void**)&wph, g_wph);
    cudaGetSymbolAddress((void**)&zh,  g_zh);

    cudaFuncSetAttribute((const void*)gemm_mma<1>, cudaFuncAttributeMaxDynamicSharedMemorySize, GSMEM);
    cudaFuncSetAttribute((const void*)gemm_mma<0>, cudaFuncAttributeMaxDynamicSharedMemorySize, GSMEM);
    cudaFuncSetAttribute((const void*)attn_mma, cudaFuncAttributeMaxDynamicSharedMemorySize, ASMEMB);

    // Prep: convert x to fp16; transpose weights
    convert_h<<<(ROWS * KDIM / 4 + 255) / 256, 256>>>(x, xh, ROWS * KDIM / 4);
    transpose_h<<<dim3(QKVN / 32, KDIM / 32), dim3(32, 8)>>>(W_attn, wah, KDIM, QKVN);
    transpose_h<<<dim3(MODEL / 32, KDIM / 32), dim3(32, 8)>>>(W_proj, wph, KDIM, MODEL);

    // QKV projection -> fp16 qkv (q pre-scaled by 1/8)
    gemm_mma<1><<<dim3(QKVN / 128, ROWS / 128), 256, GSMEM>>>(
        xh, wah, b_attn, nullptr, qh, QKVN);

    // causal attention -> z (fp16)
    attn_mma<<<dim3(SEQ / 128, HEADS, BATCH), 256, ASMEMB>>>(qh, zh);

    // output projection -> fp32 out
    gemm_mma<0><<<dim3(MODEL / 128, ROWS / 128), 256, GSMEM>>>(
        zh, wph, b_proj, out, nullptr, MODEL);
}

// round 15
// speedup vs baseline: 2.8732x; 1.0245x over previous
#include <cuda_runtime.h>
#include <cuda_fp16.h>
#include <math_constants.h>
#include <cstdint>

// Problem constants
#define BATCH 2
#define SEQ   2048
#define MODEL 1024
#define HEADS 16
#define HDIM  64
#define ROWS  (BATCH*SEQ)          // 4096
#define QKVN  (3*MODEL)            // 3072
#define KDIM  1024

// ---------------------------------------------------------------------------
// Scratch (device globals: allocation-free)
// ---------------------------------------------------------------------------
__device__ __half g_qh[(size_t)ROWS * QKVN];   // qkv hi (q pre-scaled 1/8)
__device__ __half g_xh[(size_t)ROWS * KDIM];
__device__ __half g_wah[(size_t)QKVN * KDIM];  // W_attn^T fp16
__device__ __half g_wph[(size_t)MODEL * KDIM]; // W_proj^T fp16
__device__ __half g_zh[(size_t)ROWS * MODEL];  // z fp16

// ---------------------------------------------------------------------------
// Helpers
// ---------------------------------------------------------------------------
__device__ __forceinline__ uint32_t smem_u32(const void* p) {
    uint32_t a;
    asm("{ .reg .u64 t; cvta.to.shared.u64 t, %1; cvt.u32.u64 %0, t; }"
        : "=r"(a) : "l"(p));
    return a;
}
__device__ __forceinline__ void ldm_x4(uint32_t* r, uint32_t a) {
    asm volatile("ldmatrix.sync.aligned.m8n8.x4.shared.b16 {%0,%1,%2,%3}, [%4];"
        : "=r"(r[0]), "=r"(r[1]), "=r"(r[2]), "=r"(r[3]) : "r"(a));
}
__device__ __forceinline__ void ldm_x4_t(uint32_t* r, uint32_t a) {
    asm volatile("ldmatrix.sync.aligned.m8n8.x4.trans.shared.b16 {%0,%1,%2,%3}, [%4];"
        : "=r"(r[0]), "=r"(r[1]), "=r"(r[2]), "=r"(r[3]) : "r"(a));
}
__device__ __forceinline__ void mma16816(float* c, const uint32_t* a, const uint32_t* b) {
    asm volatile("mma.sync.aligned.m16n8k16.row.col.f32.f16.f16.f32 "
        "{%0,%1,%2,%3}, {%4,%5,%6,%7}, {%8,%9}, {%0,%1,%2,%3};"
        : "+f"(c[0]), "+f"(c[1]), "+f"(c[2]), "+f"(c[3])
        : "r"(a[0]), "r"(a[1]), "r"(a[2]), "r"(a[3]), "r"(b[0]), "r"(b[1]));
}
__device__ __forceinline__ void cp16(uint32_t saddr, const void* gaddr) {
    asm volatile("cp.async.cg.shared.global [%0], [%1], 16;" :: "r"(saddr), "l"(gaddr));
}
__device__ __forceinline__ uint32_t packh2(float lo, float hi) {
    __half2 p = __floats2half2_rn(lo, hi);
    return *reinterpret_cast<uint32_t*>(&p);
}

// ---------------------------------------------------------------------------
// Fused prep: one launch does x-convert + both weight transposes.
// Block partitioning:  [0, NB_X)              : x fp32 -> fp16
//                      [NB_X, NB_X+NB_WA)     : W_attn transpose (fp16)
//                      [NB_X+NB_WA, total)    : W_proj transpose (fp16)
// ---------------------------------------------------------------------------
#define NB_X  ((ROWS * KDIM / 4) / 256)            // 4096 blocks, 4 elems/thread
#define NB_WA ((QKVN / 32) * (KDIM / 32))          // 3072 blocks
#define NB_WP ((MODEL / 32) * (KDIM / 32))         // 1024 blocks
#define NB_TOTAL (NB_X + NB_WA + NB_WP)

__global__ __launch_bounds__(256) void prep_fused(
    const float* __restrict__ x, __half* __restrict__ xh,
    const float* __restrict__ Wa, __half* __restrict__ Ta,
    const float* __restrict__ Wp, __half* __restrict__ Tp)
{
    const int bid = blockIdx.x;
    const int tid = threadIdx.x;
    if (bid < NB_X) {
        int i = bid * 256 + tid;
        float4 v = ((const float4*)x)[i];
        uint2 uh;
        uh.x = packh2(v.x, v.y);
        uh.y = packh2(v.z, v.w);
        ((uint2*)xh)[i] = uh;
        return;
    }
    // transpose path
    __shared__ float t[32][33];
    const float* W; __half* T; int Nd, n0, k0;
    if (bid < NB_X + NB_WA) {
        int b = bid - NB_X;
        W = Wa; T = Ta; Nd = QKVN;
        n0 = (b % (QKVN / 32)) * 32;
        k0 = (b / (QKVN / 32)) * 32;
    } else {
        int b = bid - NB_X - NB_WA;
        W = Wp; T = Tp; Nd = MODEL;
        n0 = (b % (MODEL / 32)) * 32;
        k0 = (b / (MODEL / 32)) * 32;
    }
    const int tx = tid & 31, ty = tid >> 5;   // 32 x 8
#pragma unroll
    for (int j = 0; j < 32; j += 8)
        t[ty + j][tx] = W[(size_t)(k0 + ty + j) * Nd + n0 + tx];
    __syncthreads();
#pragma unroll
    for (int j = 0; j < 32; j += 8) {
        int n = n0 + ty + j, k = k0 + tx;
        T[(size_t)n * KDIM + k] = __float2half_rn(t[tx][ty + j]);
    }
}

// ---------------------------------------------------------------------------
// fp16 GEMM (1-pass): C = Ah @ Bh^T + bias.  BK=64, double-buffered, 2 CTAs/SM.
// MODE 0: C = fp32.  MODE 1: Ch = fp16 of (acc+bias)*(col<MODEL ? 1/8 : 1)
// ---------------------------------------------------------------------------
#define GPITCH 144
#define GTILEB (128 * GPITCH)     // 18432
#define GSTAGEB (3 * GTILEB)      // 55296 (A, pad, B)
#define GSMEM  (2 * GSTAGEB)      // 110592

template<int MODE>
__global__ __launch_bounds__(256, 2) void gemm_mma(
    const __half* __restrict__ Ah,
    const __half* __restrict__ Bh,
    const float* __restrict__ bias, float* __restrict__ C,
    __half* __restrict__ Ch, int Nd)
{
    extern __shared__ char smem[];
    const uint32_t sbase = smem_u32(smem);
    const int tid  = threadIdx.x;
    const int wid  = tid >> 5, lane = tid & 31;
    const int bn   = blockIdx.x * 128;
    const int bm   = blockIdx.y * 128;
    const int wm0  = (wid & 3) * 32;
    const int wn0  = (wid >> 2) * 64;

    const int lrow = tid >> 3;
    const int lc   = tid & 7;

    const __half* srcA_h = Ah + (size_t)(bm + lrow) * KDIM + lc * 8;
    const __half* srcB_h = Bh + (size_t)(bn + lrow) * KDIM + lc * 8;

    const int arow  = (lane & 7) + ((lane >> 3) & 1) * 8;
    const int acolB = ((lane >> 4) & 1) * 16;
    const int brow  = (lane & 7) + ((lane >> 4) & 1) * 8;
    const int bcolB = ((lane >> 3) & 1) * 16;

    float acc[16][4];
#pragma unroll
    for (int i = 0; i < 16; i++)
#pragma unroll
        for (int j = 0; j < 4; j++) acc[i][j] = 0.f;

    auto issue = [&](int stage, int k0) {
        uint32_t so = sbase + stage * GSTAGEB + lrow * GPITCH + lc * 16;
#pragma unroll
        for (int i = 0; i < 4; i++) {
            uint32_t sa = so + i * 32 * GPITCH;
            size_t   go = (size_t)i * 32 * KDIM + k0;
            cp16(sa,              srcA_h + go);
            cp16(sa + 2 * GTILEB, srcB_h + go);
        }
        asm volatile("cp.async.commit_group;" ::: "memory");
    };

    issue(0, 0);

    for (int c = 0; c < 16; c++) {
        if (c + 1 < 16) {
            issue((c + 1) & 1, (c + 1) * 64);
            asm volatile("cp.async.wait_group 1;" ::: "memory");
        } else {
            asm volatile("cp.async.wait_group 0;" ::: "memory");
        }
        __syncthreads();

        const uint32_t ab  = sbase + (c & 1) * GSTAGEB;
        const uint32_t bb  = ab + 2 * GTILEB;

#pragma unroll
        for (int ks = 0; ks < 4; ks++) {
            uint32_t fah[2][4], fbh[4][4];
#pragma unroll
            for (int ma = 0; ma < 2; ma++) {
                uint32_t off = (uint32_t)(wm0 + ma * 16 + arow) * GPITCH + ks * 32 + acolB;
                ldm_x4(fah[ma], ab + off);
            }
#pragma unroll
            for (int na = 0; na < 4; na++) {
                uint32_t off = (uint32_t)(wn0 + na * 16 + brow) * GPITCH + ks * 32 + bcolB;
                ldm_x4(fbh[na], bb + off);
            }
#pragma unroll
            for (int ma = 0; ma < 2; ma++) {
#pragma unroll
                for (int na = 0; na < 4; na++) {
                    float* c0 = acc[ma * 8 + na * 2];
                    float* c1 = acc[ma * 8 + na * 2 + 1];
                    mma16816(c0, fah[ma], fbh[na]);
                    mma16816(c1, fah[ma], fbh[na] + 2);
                }
            }
        }
        __syncthreads();
    }

    const int er = bm + wm0 + (lane >> 2);
    const int ec = bn + wn0 + (lane & 3) * 2;
#pragma unroll
    for (int ma = 0; ma < 2; ma++) {
#pragma unroll
        for (int na = 0; na < 8; na++) {
            const float* a4 = acc[ma * 8 + na];
            int row = er + ma * 16;
            int col = ec + na * 8;
            float b0 = __ldg(bias + col), b1 = __ldg(bias + col + 1);
            if (MODE == 0) {
                float2 v0 = make_float2(a4[0] + b0, a4[1] + b1);
                float2 v1 = make_float2(a4[2] + b0, a4[3] + b1);
                *(float2*)(C + (size_t)row * Nd + col)       = v0;
                *(float2*)(C + (size_t)(row + 8) * Nd + col) = v1;
            } else {
                float sc = (col < MODEL) ? 0.125f : 1.f;
                size_t o0 = (size_t)row * Nd + col, o1 = (size_t)(row + 8) * Nd + col;
                *(uint32_t*)(Ch + o0) = packh2((a4[0] + b0) * sc, (a4[1] + b1) * sc);
                *(uint32_t*)(Ch + o1) = packh2((a4[2] + b0) * sc, (a4[3] + b1) * sc);
            }
        }
    }
}

// ---------------------------------------------------------------------------
// fp16 causal flash attention, all 1-pass. 128 q-rows/CTA, 256 threads.
// 4-stage KV ring (64-wide tiles), TWO tiles per sync-pair. 2 CTAs/SM.
// ---------------------------------------------------------------------------
#define APITCH 72                              // fp16/row (144 B)
#define AQTILE (128 * 144)                     // 18432
#define AKTILE (64 * 144)                      // 9216
#define AQH 0
#define AKV0 AQTILE                            // ring of 4 stages {Kh, Vh}
#define AKVSTAGE (2 * AKTILE)                  // 18432
#define ASMEMB (AQTILE + 4 * AKVSTAGE)         // 92160

__global__ __launch_bounds__(256, 2) void attn_mma(
    const __half* __restrict__ qh,
    __half* __restrict__ zh)
{
    extern __shared__ __half asmem[];
    const uint32_t sb = smem_u32(asmem);
    const int tid = threadIdx.x, lane = tid & 31, wid = tid >> 5;
    const int qb = gridDim.x - 1 - blockIdx.x;   // heavy tiles first
    const int h = blockIdx.y, bb = blockIdx.z;

    const size_t rowbase = (size_t)(bb * SEQ) * QKVN;
    const int hc = h * HDIM;

    auto load_q = [&] {
#pragma unroll
        for (int j = 0; j < 4; j++) {
            int c = j * 256 + tid;             // 1024 chunks
            int r = c >> 3, ch = c & 7;
            size_t g = rowbase + (size_t)(qb * 128 + r) * QKVN + hc + ch * 8;
            cp16(sb + AQH + (uint32_t)(r * 144 + ch * 16), qh + g);
        }
    };
    auto load_kv = [&](int stage, int kb) {
        uint32_t sbb = sb + AKV0 + stage * AKVSTAGE;
#pragma unroll
        for (int j = 0; j < 2; j++) {
            int c = j * 256 + tid;             // 512 chunks
            int r = c >> 3, ch = c & 7;
            size_t gk = rowbase + (size_t)(kb * 64 + r) * QKVN + MODEL + hc + ch * 8;
            uint32_t d = (uint32_t)(r * 144 + ch * 16);
            cp16(sbb + d,          qh + gk);           // K hi
            cp16(sbb + AKTILE + d, qh + gk + MODEL);   // V hi
        }
    };

    const int arow  = (lane & 7) + ((lane >> 3) & 1) * 8;
    const int acolB = ((lane >> 4) & 1) * 16;
    const int brow  = (lane & 7) + ((lane >> 4) & 1) * 8;
    const int bcolB = ((lane >> 3) & 1) * 16;
    const int vrow  = (lane & 7) + ((lane >> 3) & 1) * 8;
    const int vcol8 = ((lane >> 4) & 1) * 8;

    const int wr0 = qb * 128 + wid * 16;       // warp's global row base

    uint32_t qfh[4][4];
    float m0 = -CUDART_INF_F, m1 = -CUDART_INF_F, l0 = 0.f, l1 = 0.f;
    float o[8][4];
#pragma unroll
    for (int i = 0; i < 8; i++)
#pragma unroll
        for (int j = 0; j < 4; j++) o[i][j] = 0.f;

    // per-tile body (guarded by causal skip)
    auto tile_body = [&](int kb) {
        if (kb * 64 > wr0 + 15) return;        // warp fully above diagonal
        const uint32_t kvb = sb + AKV0 + (kb & 3) * AKVSTAGE;
        const uint32_t kh_b = kvb;
        const uint32_t vh_b = kvb + AKTILE;

        // ---- S = Q K^T ----
        float s[8][4];
#pragma unroll
        for (int i = 0; i < 8; i++)
#pragma unroll
            for (int j = 0; j < 4; j++) s[i][j] = 0.f;
#pragma unroll
        for (int ks = 0; ks < 4; ks++) {
#pragma unroll
            for (int np = 0; np < 4; np++) {
                uint32_t off = (uint32_t)(np * 16 + brow) * (APITCH * 2) + ks * 32 + bcolB;
                uint32_t kh4[4];
                ldm_x4(kh4, kh_b + off);
                mma16816(s[2*np],   qfh[ks], kh4 + 0);
                mma16816(s[2*np+1], qfh[ks], kh4 + 2);
            }
        }

        // ---- causal mask on diagonal-overlapping tiles ----
        if (kb * 64 + 63 > wr0) {
            const int rr0 = wr0 + (lane >> 2);
            const int cc0 = kb * 64 + (lane & 3) * 2;
#pragma unroll
            for (int nt = 0; nt < 8; nt++) {
#pragma unroll
                for (int jj = 0; jj < 2; jj++) {
                    int col = cc0 + nt * 8 + jj;
                    if (col > rr0)     s[nt][jj]     = -CUDART_INF_F;
                    if (col > rr0 + 8) s[nt][2 + jj] = -CUDART_INF_F;
                }
            }
        }

        // ---- online softmax ----
        float mx0 = -CUDART_INF_F, mx1 = -CUDART_INF_F;
#pragma unroll
        for (int nt = 0; nt < 8; nt++) {
            mx0 = fmaxf(mx0, fmaxf(s[nt][0], s[nt][1]));
            mx1 = fmaxf(mx1, fmaxf(s[nt][2], s[nt][3]));
        }
        mx0 = fmaxf(mx0, __shfl_xor_sync(0xffffffffu, mx0, 1));
        mx0 = fmaxf(mx0, __shfl_xor_sync(0xffffffffu, mx0, 2));
        mx1 = fmaxf(mx1, __shfl_xor_sync(0xffffffffu, mx1, 1));
        mx1 = fmaxf(mx1, __shfl_xor_sync(0xffffffffu, mx1, 2));
        const float mn0 = fmaxf(m0, mx0), mn1 = fmaxf(m1, mx1);
        const float cr0 = __expf(m0 - mn0), cr1 = __expf(m1 - mn1);
        float sum0 = 0.f, sum1 = 0.f;
        uint32_t pah[4][4];
#pragma unroll
        for (int kt = 0; kt < 4; kt++) {
#pragma unroll
            for (int hh = 0; hh < 2; hh++) {
                const int nt = 2 * kt + hh;
                float p00 = __expf(s[nt][0] - mn0);
                float p01 = __expf(s[nt][1] - mn0);
                float p10 = __expf(s[nt][2] - mn1);
                float p11 = __expf(s[nt][3] - mn1);
                sum0 += p00 + p01;
                sum1 += p10 + p11;
                pah[kt][hh * 2 + 0] = packh2(p00, p01);
                pah[kt][hh * 2 + 1] = packh2(p10, p11);
            }
        }
        sum0 += __shfl_xor_sync(0xffffffffu, sum0, 1);
        sum0 += __shfl_xor_sync(0xffffffffu, sum0, 2);
        sum1 += __shfl_xor_sync(0xffffffffu, sum1, 1);
        sum1 += __shfl_xor_sync(0xffffffffu, sum1, 2);
        l0 = l0 * cr0 + sum0;  m0 = mn0;
        l1 = l1 * cr1 + sum1;  m1 = mn1;
#pragma unroll
        for (int nt = 0; nt < 8; nt++) {
            o[nt][0] *= cr0; o[nt][1] *= cr0;
            o[nt][2] *= cr1; o[nt][3] *= cr1;
        }

        // ---- O += P V ----
#pragma unroll
        for (int kt = 0; kt < 4; kt++) {
#pragma unroll
            for (int p = 0; p < 4; p++) {
                uint32_t off = (uint32_t)(kt * 16 + vrow) * (APITCH * 2)
                             + (uint32_t)(p * 16 + vcol8) * 2;
                uint32_t fvh[4];
                ldm_x4_t(fvh, vh_b + off);
                mma16816(o[2*p],   pah[kt], fvh + 0);
                mma16816(o[2*p+1], pah[kt], fvh + 2);
            }
        }
    };

    // prologue: Q + first tile pair
    load_q();
    load_kv(0, 0);
    load_kv(1, 1);
    asm volatile("cp.async.commit_group;" ::: "memory");

    const int pmax = qb;                       // pairs 0..qb  (tiles 2p, 2p+1)
    for (int p = 0; p <= pmax; p++) {
        if (p < pmax) {
            load_kv((2 * p + 2) & 3, 2 * p + 2);
            load_kv((2 * p + 3) & 3, 2 * p + 3);
            asm volatile("cp.async.commit_group;" ::: "memory");
            asm volatile("cp.async.wait_group 1;" ::: "memory");
        } else {
            asm volatile("cp.async.wait_group 0;" ::: "memory");
        }
        __syncthreads();

        if (p == 0) {
#pragma unroll
            for (int ks = 0; ks < 4; ks++) {
                uint32_t off = (uint32_t)(wid * 16 + arow) * (APITCH * 2) + ks * 32 + acolB;
                ldm_x4(qfh[ks], sb + AQH + off);
            }
        }

        tile_body(2 * p);
        tile_body(2 * p + 1);
        __syncthreads();
    }

    // ---- epilogue: normalize, store z ----
    const float inv0 = 1.f / l0, inv1 = 1.f / l1;
    const int gr0 = bb * SEQ + qb * 128 + wid * 16 + (lane >> 2);
    const int gc  = h * HDIM + (lane & 3) * 2;
#pragma unroll
    for (int nt = 0; nt < 8; nt++) {
        size_t off0 = (size_t)gr0 * MODEL + gc + nt * 8;
        size_t off1 = (size_t)(gr0 + 8) * MODEL + gc + nt * 8;
        *(uint32_t*)(zh + off0) = packh2(o[nt][0] * inv0, o[nt][1] * inv0);
        *(uint32_t*)(zh + off1) = packh2(o[nt][2] * inv1, o[nt][3] * inv1);
    }
}

// ---------------------------------------------------------------------------
// Launch
// ---------------------------------------------------------------------------
extern "C" void kernel_launch(void* const* d_in, const int* in_sizes, int n_in,
                              void* d_out, int out_size)
{
    const float* x      = (const float*)d_in[0];
    const float* W_attn = (const float*)d_in[1];
    const float* b_attn = (const float*)d_in[2];
    const float* W_proj = (const float*)d_in[3];
    const float* b_proj = (const float*)d_in[4];
    float* out = (float*)d_out;

    __half *qh, *xh, *wah, *wph, *zh;
    cudaGetSymbolAddress((void**)&qh,  g_qh);
    cudaGetSymbolAddress((void**)&xh,  g_xh);
    cudaGetSymbolAddress((void**)&wah, g_wah);
    cudaGetSymbolAddress((void**)&wph, g_wph);
    cudaGetSymbolAddress((void**)&zh,  g_zh);

    cudaFuncSetAttribute((const void*)gemm_mma<1>, cudaFuncAttributeMaxDynamicSharedMemorySize, GSMEM);
    cudaFuncSetAttribute((const void*)gemm_mma<0>, cudaFuncAttributeMaxDynamicSharedMemorySize, GSMEM);
    cudaFuncSetAttribute((const void*)attn_mma, cudaFuncAttributeMaxDynamicSharedMemorySize, ASMEMB);

    // Fused prep: x convert + both weight transposes in one launch
    prep_fused<<<NB_TOTAL, 256>>>(x, xh, W_attn, wah, W_proj, wph);

    // QKV projection -> fp16 qkv (q pre-scaled by 1/8)
    gemm_mma<1><<<dim3(QKVN / 128, ROWS / 128), 256, GSMEM>>>(
        xh, wah, b_attn, nullptr, qh, QKVN);

    // causal attention -> z (fp16)
    attn_mma<<<dim3(SEQ / 128, HEADS, BATCH), 256, ASMEMB>>>(qh, zh);

    // output projection -> fp32 out
    gemm_mma<0><<<dim3(MODEL / 128, ROWS / 128), 256, GSMEM>>>(
        zh, wph, b_proj, out, nullptr, MODEL);
}